// round 2
// baseline (speedup 1.0000x reference)
#include <cuda_runtime.h>
#include <math.h>

// Problem constants
#define Bsz 2
#define Slen 2048
#define Dm 512
#define Hh 8
#define Aa 64
#define Ll 2
#define Tt 256
#define Mrows (Bsz*Slen)   // 4096
#define LN_EPS 1e-5f

// ---------------- scratch (device globals; no allocation allowed) ----------
__device__ float g_x[Mrows*Dm];            // running activations [B*S, D]
__device__ float g_q[Bsz*Hh*Slen*Aa];      // [B,H,S,A]
__device__ float g_k[Bsz*Hh*Slen*Aa];
__device__ float g_v[Bsz*Hh*Slen*Aa];
__device__ float g_heads[Mrows*Hh*Aa];     // [B,S,H*A]
__device__ float g_tmp[Mrows*Dm];
__device__ float g_h1[Mrows*Dm];

// ---------------------------------------------------------------------------
// QKV projection: for head h, out[b,h,s,a] = sum_d x[b,s,d] * W[h,d,a] + bias[h,a]
// grid = (H, Mrows/64, 3), block = 256. 64x64 tile, 4x4 microtile.
// ---------------------------------------------------------------------------
__global__ __launch_bounds__(256)
void qkv_kernel(const float* __restrict__ x,
                const float* __restrict__ Wq, const float* __restrict__ Wk,
                const float* __restrict__ Wv,
                const float* __restrict__ bq, const float* __restrict__ bk,
                const float* __restrict__ bv,
                float* __restrict__ Q, float* __restrict__ K, float* __restrict__ V)
{
    const float* W; const float* bias; float* out;
    int z = blockIdx.z;
    if (z == 0)      { W = Wq; bias = bq; out = Q; }
    else if (z == 1) { W = Wk; bias = bk; out = K; }
    else             { W = Wv; bias = bv; out = V; }

    const int h  = blockIdx.x;       // head (N-tile of width 64 == A)
    const int m0 = blockIdx.y * 64;

    __shared__ float As[16][64];     // [kk][m]
    __shared__ float Bs[16][64];     // [kk][a]

    const int tid = threadIdx.x;
    const int ty = tid / 16, tx = tid % 16;

    float acc[4][4] = {};
    const float* Wh = W + (size_t)h * Dm * Aa;  // element (d,a) at Wh[d*64 + a]

    for (int kt = 0; kt < Dm; kt += 16) {
        {   // A tile: 64 rows x 16 k, one float4 per thread
            int row = tid >> 2;          // 0..63
            int q4  = tid & 3;           // 0..3
            float4 va = *reinterpret_cast<const float4*>(&x[(size_t)(m0 + row) * Dm + kt + q4 * 4]);
            As[q4*4+0][row] = va.x; As[q4*4+1][row] = va.y;
            As[q4*4+2][row] = va.z; As[q4*4+3][row] = va.w;
        }
        {   // B tile: 16 k x 64 a, one float4 per thread
            int kk = tid >> 4;           // 0..15
            int a4 = tid & 15;           // 0..15
            float4 vb = *reinterpret_cast<const float4*>(&Wh[(size_t)(kt + kk) * Aa + a4 * 4]);
            Bs[kk][a4*4+0] = vb.x; Bs[kk][a4*4+1] = vb.y;
            Bs[kk][a4*4+2] = vb.z; Bs[kk][a4*4+3] = vb.w;
        }
        __syncthreads();
        #pragma unroll
        for (int kk = 0; kk < 16; kk++) {
            float a_[4], b_[4];
            #pragma unroll
            for (int i = 0; i < 4; i++) a_[i] = As[kk][ty*4 + i];
            #pragma unroll
            for (int j = 0; j < 4; j++) b_[j] = Bs[kk][tx*4 + j];
            #pragma unroll
            for (int i = 0; i < 4; i++)
                #pragma unroll
                for (int j = 0; j < 4; j++)
                    acc[i][j] = fmaf(a_[i], b_[j], acc[i][j]);
        }
        __syncthreads();
    }

    #pragma unroll
    for (int i = 0; i < 4; i++) {
        int m = m0 + ty*4 + i;
        int b_ = m / Slen, s = m % Slen;
        #pragma unroll
        for (int j = 0; j < 4; j++) {
            int a = tx*4 + j;
            out[(((size_t)(b_*Hh + h) * Slen) + s) * Aa + a] = acc[i][j] + bias[h*Aa + a];
        }
    }
}

// ---------------------------------------------------------------------------
// Generic tiled GEMM: C[M,N] = A[M,K] @ B[K,N] + bias[N]   (optional ReLU)
// grid = (N/64, M/64), block = 256.  M is always Mrows-compatible tiles.
// ---------------------------------------------------------------------------
__global__ __launch_bounds__(256)
void gemm_kernel(const float* __restrict__ Amat, const float* __restrict__ Bmat,
                 const float* __restrict__ bias, float* __restrict__ C,
                 int N, int Kd, int relu)
{
    const int n0 = blockIdx.x * 64;
    const int m0 = blockIdx.y * 64;

    __shared__ float As[16][64];   // [kk][m]
    __shared__ float Bs[16][64];   // [kk][n]

    const int tid = threadIdx.x;
    const int ty = tid / 16, tx = tid % 16;

    float acc[4][4] = {};

    for (int kt = 0; kt < Kd; kt += 16) {
        {
            int row = tid >> 2;
            int q4  = tid & 3;
            float4 va = *reinterpret_cast<const float4*>(&Amat[(size_t)(m0 + row) * Kd + kt + q4 * 4]);
            As[q4*4+0][row] = va.x; As[q4*4+1][row] = va.y;
            As[q4*4+2][row] = va.z; As[q4*4+3][row] = va.w;
        }
        {
            int kk = tid >> 4;
            int n4 = tid & 15;
            float4 vb = *reinterpret_cast<const float4*>(&Bmat[(size_t)(kt + kk) * N + n0 + n4 * 4]);
            Bs[kk][n4*4+0] = vb.x; Bs[kk][n4*4+1] = vb.y;
            Bs[kk][n4*4+2] = vb.z; Bs[kk][n4*4+3] = vb.w;
        }
        __syncthreads();
        #pragma unroll
        for (int kk = 0; kk < 16; kk++) {
            float a_[4], b_[4];
            #pragma unroll
            for (int i = 0; i < 4; i++) a_[i] = As[kk][ty*4 + i];
            #pragma unroll
            for (int j = 0; j < 4; j++) b_[j] = Bs[kk][tx*4 + j];
            #pragma unroll
            for (int i = 0; i < 4; i++)
                #pragma unroll
                for (int j = 0; j < 4; j++)
                    acc[i][j] = fmaf(a_[i], b_[j], acc[i][j]);
        }
        __syncthreads();
    }

    #pragma unroll
    for (int i = 0; i < 4; i++) {
        int m = m0 + ty*4 + i;
        #pragma unroll
        for (int j = 0; j < 4; j++) {
            int n = n0 + tx*4 + j;
            float v = acc[i][j] + bias[n];
            if (relu) v = fmaxf(v, 0.0f);
            C[(size_t)m * N + n] = v;
        }
    }
}

// ---------------------------------------------------------------------------
// Flash attention: per (b,h), 64-query-row tiles, online softmax over S=2048.
// block = 256 (16x16 threads, 4x4 microtiles). Dynamic smem = 3 * 64*65 floats.
// K-tile buffer is reused for the P (probability) tile.
// heads layout: [B, S, H*A] (concat-ready).
// ---------------------------------------------------------------------------
__global__ __launch_bounds__(256)
void flash_kernel(const float* __restrict__ Q, const float* __restrict__ K,
                  const float* __restrict__ V, float* __restrict__ heads)
{
    extern __shared__ float sm[];
    float* Qs  = sm;               // [64][65] query tile (row-major, row*65+k)
    float* KPs = sm + 64*65;       // [64][65] K tile, reused as P tile
    float* Vs  = sm + 2*64*65;     // [64][65]

    const int s0 = blockIdx.x * 64;
    const int h  = blockIdx.y;
    const int b  = blockIdx.z;

    const float* Qbh = Q + ((size_t)(b*Hh + h) * Slen) * Aa;
    const float* Kbh = K + ((size_t)(b*Hh + h) * Slen) * Aa;
    const float* Vbh = V + ((size_t)(b*Hh + h) * Slen) * Aa;

    const int tid = threadIdx.x;
    const int ty = tid / 16, tx = tid % 16;

    // Load Q tile (64x64 floats = 1024 float4; 4 per thread)
    #pragma unroll
    for (int it = 0; it < 4; it++) {
        int idx = tid + it * 256;         // 0..1023
        int r = idx >> 4, q4 = idx & 15;
        float4 vq = *reinterpret_cast<const float4*>(&Qbh[(size_t)(s0 + r) * Aa + q4 * 4]);
        Qs[r*65 + q4*4 + 0] = vq.x; Qs[r*65 + q4*4 + 1] = vq.y;
        Qs[r*65 + q4*4 + 2] = vq.z; Qs[r*65 + q4*4 + 3] = vq.w;
    }

    float m_run[4], l_run[4], O[4][4];
    #pragma unroll
    for (int i = 0; i < 4; i++) {
        m_run[i] = -INFINITY; l_run[i] = 0.0f;
        #pragma unroll
        for (int j = 0; j < 4; j++) O[i][j] = 0.0f;
    }
    const float scale = 0.125f;  // 1/sqrt(64)

    for (int c0 = 0; c0 < Slen; c0 += 64) {
        // Load K and V tiles
        #pragma unroll
        for (int it = 0; it < 4; it++) {
            int idx = tid + it * 256;
            int r = idx >> 4, q4 = idx & 15;
            float4 vk = *reinterpret_cast<const float4*>(&Kbh[(size_t)(c0 + r) * Aa + q4 * 4]);
            KPs[r*65 + q4*4 + 0] = vk.x; KPs[r*65 + q4*4 + 1] = vk.y;
            KPs[r*65 + q4*4 + 2] = vk.z; KPs[r*65 + q4*4 + 3] = vk.w;
            float4 vv = *reinterpret_cast<const float4*>(&Vbh[(size_t)(c0 + r) * Aa + q4 * 4]);
            Vs[r*65 + q4*4 + 0] = vv.x; Vs[r*65 + q4*4 + 1] = vv.y;
            Vs[r*65 + q4*4 + 2] = vv.z; Vs[r*65 + q4*4 + 3] = vv.w;
        }
        __syncthreads();

        // S = Q @ K^T (4x4 per thread)
        float sv[4][4] = {};
        #pragma unroll 8
        for (int kk = 0; kk < 64; kk++) {
            float a_[4], b_[4];
            #pragma unroll
            for (int i = 0; i < 4; i++) a_[i] = Qs[(ty*4 + i)*65 + kk];
            #pragma unroll
            for (int j = 0; j < 4; j++) b_[j] = KPs[(tx*4 + j)*65 + kk];
            #pragma unroll
            for (int i = 0; i < 4; i++)
                #pragma unroll
                for (int j = 0; j < 4; j++)
                    sv[i][j] = fmaf(a_[i], b_[j], sv[i][j]);
        }

        // Online softmax update (row groups: 16 threads with same ty share 4 rows)
        float m_new[4], fac[4], psum[4];
        #pragma unroll
        for (int i = 0; i < 4; i++) {
            float tmax = -INFINITY;
            #pragma unroll
            for (int j = 0; j < 4; j++) {
                sv[i][j] *= scale;
                tmax = fmaxf(tmax, sv[i][j]);
            }
            #pragma unroll
            for (int off = 8; off >= 1; off >>= 1)
                tmax = fmaxf(tmax, __shfl_xor_sync(0xffffffffu, tmax, off));
            m_new[i] = fmaxf(m_run[i], tmax);
            fac[i]   = __expf(m_run[i] - m_new[i]);
            float ps = 0.0f;
            #pragma unroll
            for (int j = 0; j < 4; j++) {
                float p = __expf(sv[i][j] - m_new[i]);
                sv[i][j] = p;
                ps += p;
            }
            #pragma unroll
            for (int off = 8; off >= 1; off >>= 1)
                ps += __shfl_xor_sync(0xffffffffu, ps, off);
            psum[i] = ps;
        }
        #pragma unroll
        for (int i = 0; i < 4; i++) {
            l_run[i] = l_run[i] * fac[i] + psum[i];
            m_run[i] = m_new[i];
            #pragma unroll
            for (int j = 0; j < 4; j++) O[i][j] *= fac[i];
        }

        __syncthreads();   // everyone done reading K before P overwrite
        #pragma unroll
        for (int i = 0; i < 4; i++)
            #pragma unroll
            for (int j = 0; j < 4; j++)
                KPs[(ty*4 + i)*65 + tx*4 + j] = sv[i][j];
        __syncthreads();

        // O += P @ V
        #pragma unroll 8
        for (int cc = 0; cc < 64; cc++) {
            float p_[4], v_[4];
            #pragma unroll
            for (int i = 0; i < 4; i++) p_[i] = KPs[(ty*4 + i)*65 + cc];
            #pragma unroll
            for (int j = 0; j < 4; j++) v_[j] = Vs[cc*65 + tx*4 + j];
            #pragma unroll
            for (int i = 0; i < 4; i++)
                #pragma unroll
                for (int j = 0; j < 4; j++)
                    O[i][j] = fmaf(p_[i], v_[j], O[i][j]);
        }
        __syncthreads();   // before reloading K/V tiles
    }

    // Normalize + write: heads[b, s, h*A + a]
    #pragma unroll
    for (int i = 0; i < 4; i++) {
        float inv = 1.0f / l_run[i];
        int s = s0 + ty*4 + i;
        #pragma unroll
        for (int j = 0; j < 4; j++) {
            int a = tx*4 + j;
            heads[(((size_t)b * Slen + s) * Hh + h) * Aa + a] = O[i][j] * inv;
        }
    }
}

// ---------------------------------------------------------------------------
// Fused residual-add + LayerNorm (in-place on x): x = LN(x + t) * g + beta
// grid = Mrows, block = 256 (each thread owns 2 of the 512 columns)
// ---------------------------------------------------------------------------
__global__ __launch_bounds__(256)
void addln_kernel(float* __restrict__ x, const float* __restrict__ t,
                  const float* __restrict__ g, const float* __restrict__ beta)
{
    const int r = blockIdx.x;
    const int tid = threadIdx.x;
    float v0 = x[(size_t)r*Dm + tid]       + t[(size_t)r*Dm + tid];
    float v1 = x[(size_t)r*Dm + 256 + tid] + t[(size_t)r*Dm + 256 + tid];

    float s  = v0 + v1;
    float ss = v0*v0 + v1*v1;
    #pragma unroll
    for (int off = 16; off >= 1; off >>= 1) {
        s  += __shfl_xor_sync(0xffffffffu, s,  off);
        ss += __shfl_xor_sync(0xffffffffu, ss, off);
    }
    __shared__ float red_s[8], red_ss[8];
    __shared__ float sm_mean, sm_rstd;
    int wid = tid >> 5, lane = tid & 31;
    if (lane == 0) { red_s[wid] = s; red_ss[wid] = ss; }
    __syncthreads();
    if (tid == 0) {
        float S = 0.0f, SS = 0.0f;
        #pragma unroll
        for (int w = 0; w < 8; w++) { S += red_s[w]; SS += red_ss[w]; }
        float mean = S * (1.0f / Dm);
        float var  = SS * (1.0f / Dm) - mean * mean;
        sm_mean = mean;
        sm_rstd = rsqrtf(var + LN_EPS);
    }
    __syncthreads();
    float mean = sm_mean, rstd = sm_rstd;
    x[(size_t)r*Dm + tid]       = (v0 - mean) * rstd * g[tid]       + beta[tid];
    x[(size_t)r*Dm + 256 + tid] = (v1 - mean) * rstd * g[256 + tid] + beta[256 + tid];
}

// ---------------------------------------------------------------------------
extern "C" void kernel_launch(void* const* d_in, const int* in_sizes, int n_in,
                              void* d_out, int out_size)
{
    const float* x    = (const float*)d_in[0];
    const float* Wq   = (const float*)d_in[1];
    const float* bq   = (const float*)d_in[2];
    const float* Wk   = (const float*)d_in[3];
    const float* bk   = (const float*)d_in[4];
    const float* Wv   = (const float*)d_in[5];
    const float* bv   = (const float*)d_in[6];
    const float* Wo   = (const float*)d_in[7];
    const float* bo   = (const float*)d_in[8];
    const float* ln1g = (const float*)d_in[9];
    const float* ln1b = (const float*)d_in[10];
    const float* W1   = (const float*)d_in[11];
    const float* b1   = (const float*)d_in[12];
    const float* W2   = (const float*)d_in[13];
    const float* b2   = (const float*)d_in[14];
    const float* ln2g = (const float*)d_in[15];
    const float* ln2b = (const float*)d_in[16];
    const float* Wp   = (const float*)d_in[17];
    const float* bp   = (const float*)d_in[18];

    float *gx, *gq, *gk, *gv, *gh, *gt, *g1;
    cudaGetSymbolAddress((void**)&gx, g_x);
    cudaGetSymbolAddress((void**)&gq, g_q);
    cudaGetSymbolAddress((void**)&gk, g_k);
    cudaGetSymbolAddress((void**)&gv, g_v);
    cudaGetSymbolAddress((void**)&gh, g_heads);
    cudaGetSymbolAddress((void**)&gt, g_tmp);
    cudaGetSymbolAddress((void**)&g1, g_h1);

    const int flash_smem = 3 * 64 * 65 * (int)sizeof(float);   // 49920 B
    cudaFuncSetAttribute(flash_kernel, cudaFuncAttributeMaxDynamicSharedMemorySize,
                         flash_smem);

    cudaMemcpyAsync(gx, x, (size_t)Mrows * Dm * sizeof(float),
                    cudaMemcpyDeviceToDevice);

    for (int l = 0; l < Ll; l++) {
        const float* Wq_l = Wq + (size_t)l * Hh * Dm * Aa;
        const float* Wk_l = Wk + (size_t)l * Hh * Dm * Aa;
        const float* Wv_l = Wv + (size_t)l * Hh * Dm * Aa;
        const float* bq_l = bq + (size_t)l * Hh * Aa;
        const float* bk_l = bk + (size_t)l * Hh * Aa;
        const float* bv_l = bv + (size_t)l * Hh * Aa;
        const float* Wo_l = Wo + (size_t)l * (Hh*Aa) * Dm;
        const float* bo_l = bo + (size_t)l * Dm;
        const float* W1_l = W1 + (size_t)l * Dm * Dm;
        const float* b1_l = b1 + (size_t)l * Dm;
        const float* W2_l = W2 + (size_t)l * Dm * Dm;
        const float* b2_l = b2 + (size_t)l * Dm;

        // QKV projections
        qkv_kernel<<<dim3(Hh, Mrows/64, 3), 256>>>(
            gx, Wq_l, Wk_l, Wv_l, bq_l, bk_l, bv_l, gq, gk, gv);

        // Flash attention -> heads [B,S,H*A]
        flash_kernel<<<dim3(Slen/64, Hh, Bsz), 256, flash_smem>>>(gq, gk, gv, gh);

        // Output projection
        gemm_kernel<<<dim3(Dm/64, Mrows/64), 256>>>(gh, Wo_l, bo_l, gt, Dm, Hh*Aa, 0);
        // AddNorm 1 (in-place on gx)
        addln_kernel<<<Mrows, 256>>>(gx, gt, ln1g + (size_t)l*Dm, ln1b + (size_t)l*Dm);

        // FFN
        gemm_kernel<<<dim3(Dm/64, Mrows/64), 256>>>(gx, W1_l, b1_l, g1, Dm, Dm, 1);
        gemm_kernel<<<dim3(Dm/64, Mrows/64), 256>>>(g1, W2_l, b2_l, gt, Dm, Dm, 0);
        // AddNorm 2
        addln_kernel<<<Mrows, 256>>>(gx, gt, ln2g + (size_t)l*Dm, ln2b + (size_t)l*Dm);
    }

    // Final projection to target_dim
    gemm_kernel<<<dim3(Tt/64, Mrows/64), 256>>>(gx, Wp, bp, (float*)d_out, Tt, Dm, 0);
}

// round 4
// speedup vs baseline: 1.2982x; 1.2982x over previous
#include <cuda_runtime.h>
#include <cuda_bf16.h>
#include <math.h>
#include <stdint.h>

#define Bsz 2
#define Slen 2048
#define Dm 512
#define Hh 8
#define Aa 64
#define Ll 2
#define Tt 256
#define Mrows (Bsz*Slen)
#define LN_EPS 1e-5f

__device__ float g_x[Mrows*Dm];
__device__ float g_q[Bsz*Hh*Slen*Aa];
__device__ float g_k[Bsz*Hh*Slen*Aa];
__device__ float g_v[Bsz*Hh*Slen*Aa];
__device__ float g_heads[Mrows*Hh*Aa];
__device__ float g_tmp[Mrows*Dm];
__device__ float g_h1[Mrows*Dm];
// bf16 hi/lo pre-transposed weights, layout [N][K=512]
__device__ __nv_bfloat16 g_wqkv_h[Ll*1536*512];
__device__ __nv_bfloat16 g_wqkv_l[Ll*1536*512];
__device__ __nv_bfloat16 g_wo_h[Ll*512*512];
__device__ __nv_bfloat16 g_wo_l[Ll*512*512];
__device__ __nv_bfloat16 g_w1_h[Ll*512*512];
__device__ __nv_bfloat16 g_w1_l[Ll*512*512];
__device__ __nv_bfloat16 g_w2_h[Ll*512*512];
__device__ __nv_bfloat16 g_w2_l[Ll*512*512];
__device__ __nv_bfloat16 g_wp_h[Tt*512];
__device__ __nv_bfloat16 g_wp_l[Tt*512];

__device__ __forceinline__ uint32_t smem_u32(const void* p) {
    uint32_t a;
    asm("{ .reg .u64 t; cvta.to.shared.u64 t, %1; cvt.u32.u64 %0, t; }" : "=r"(a) : "l"(p));
    return a;
}
__device__ __forceinline__ uint32_t pack2(float x, float y) {
    return (uint32_t)__bfloat16_as_ushort(__float2bfloat16(x)) |
           ((uint32_t)__bfloat16_as_ushort(__float2bfloat16(y)) << 16);
}
__device__ __forceinline__ void ldsm4(uint32_t* r, uint32_t addr) {
    asm volatile("ldmatrix.sync.aligned.m8n8.x4.shared.b16 {%0,%1,%2,%3}, [%4];"
        : "=r"(r[0]), "=r"(r[1]), "=r"(r[2]), "=r"(r[3]) : "r"(addr));
}
__device__ __forceinline__ void mma16816(float* d, const uint32_t* a, const uint32_t* b) {
    asm volatile("mma.sync.aligned.m16n8k16.row.col.f32.bf16.bf16.f32 "
        "{%0,%1,%2,%3}, {%4,%5,%6,%7}, {%8,%9}, {%0,%1,%2,%3};"
        : "+f"(d[0]), "+f"(d[1]), "+f"(d[2]), "+f"(d[3])
        : "r"(a[0]), "r"(a[1]), "r"(a[2]), "r"(a[3]), "r"(b[0]), "r"(b[1]));
}

// ---- weight prep: transpose [K=512,N] fp32 -> [N][512] bf16 hi/lo ----
__global__ void prep_w(const float* __restrict__ W, __nv_bfloat16* __restrict__ hi,
                       __nv_bfloat16* __restrict__ lo, int N)
{
    int l = blockIdx.z;
    const float* Wl = W + (size_t)l * 512 * N;
    __nv_bfloat16* hiL = hi + (size_t)l * N * 512;
    __nv_bfloat16* loL = lo + (size_t)l * N * 512;
    __shared__ float t[32][33];
    int k0 = blockIdx.x * 32, n0 = blockIdx.y * 32;
    for (int i = threadIdx.y; i < 32; i += 8)
        t[i][threadIdx.x] = Wl[(size_t)(k0 + i) * N + n0 + threadIdx.x];
    __syncthreads();
    for (int i = threadIdx.y; i < 32; i += 8) {
        float v = t[threadIdx.x][i];
        __nv_bfloat16 h = __float2bfloat16(v);
        hiL[(size_t)(n0 + i) * 512 + k0 + threadIdx.x] = h;
        loL[(size_t)(n0 + i) * 512 + k0 + threadIdx.x] = __float2bfloat16(v - __bfloat162float(h));
    }
}
// QKV: Wz[L,H,D,A] -> [L*1536][512], n = l*1536 + z*512 + h*64 + a
__global__ void prep_qkv_w(const float* __restrict__ Wq, const float* __restrict__ Wk,
                           const float* __restrict__ Wv,
                           __nv_bfloat16* __restrict__ hi, __nv_bfloat16* __restrict__ lo)
{
    int bz = blockIdx.z;
    int l = bz / 24, rem = bz % 24, zz = rem / 8, h = rem % 8;
    const float* W = (zz == 0 ? Wq : zz == 1 ? Wk : Wv) + ((size_t)(l * Hh + h)) * Dm * Aa;
    size_t nb = (size_t)l * 1536 + zz * 512 + h * 64;
    __shared__ float t[32][33];
    int d0 = blockIdx.x * 32, a0 = blockIdx.y * 32;
    for (int i = threadIdx.y; i < 32; i += 8)
        t[i][threadIdx.x] = W[(size_t)(d0 + i) * Aa + a0 + threadIdx.x];
    __syncthreads();
    for (int i = threadIdx.y; i < 32; i += 8) {
        float v = t[threadIdx.x][i];
        __nv_bfloat16 hv = __float2bfloat16(v);
        hi[(nb + a0 + i) * 512 + d0 + threadIdx.x] = hv;
        lo[(nb + a0 + i) * 512 + d0 + threadIdx.x] = __float2bfloat16(v - __bfloat162float(hv));
    }
}

// ---------------------------------------------------------------------------
// HMMA GEMM: C[4096,N] = A[4096,512]fp32 @ B(hi/lo)[N][512]^T + bias.
// bf16 hi/lo split: C = Ah*Bh + Ah*Bl + Al*Bh (fp32 accum).
// BM=128 BN=128 BK=64. block=256 (8 warps, each 64x32). grid (N/128, 32).
// Smem rows strided 72 bf16 (144B) -> conflict-free ldmatrix.
// ---------------------------------------------------------------------------
#define RS 72     // row stride in bf16 elements
#define RSB 144   // row stride bytes

__global__ __launch_bounds__(256)
void gemm_mma(const float* __restrict__ A,
              const __nv_bfloat16* __restrict__ Bh_g, const __nv_bfloat16* __restrict__ Bl_g,
              const float* __restrict__ bias0, const float* __restrict__ bias1,
              const float* __restrict__ bias2,
              float* __restrict__ C0, float* __restrict__ C1, float* __restrict__ C2,
              int ldC, int relu, int qkv)
{
    extern __shared__ char smem[];
    // carve: Ah [128][72], Al, Bh, Bl (bf16)
    char* pAh = smem;
    char* pAl = smem + 128*RSB;
    char* pBh = smem + 2*128*RSB;
    char* pBl = smem + 3*128*RSB;
    const uint32_t uAh = smem_u32(pAh), uAl = smem_u32(pAl);
    const uint32_t uBh = smem_u32(pBh), uBl = smem_u32(pBl);

    const int tid = threadIdx.x;
    const int wid = tid >> 5, lid = tid & 31;
    const int wm = wid >> 2, wn = wid & 3;       // warp tile: (wm*64, wn*32)
    const int g = lid >> 2, tg = lid & 3;
    const int m0 = blockIdx.y * 128, n0 = blockIdx.x * 128;

    float acc[4][4][4];
    #pragma unroll
    for (int i = 0; i < 4; i++)
        #pragma unroll
        for (int j = 0; j < 4; j++)
            #pragma unroll
            for (int e = 0; e < 4; e++) acc[i][j][e] = 0.0f;

    // ldmatrix lane address components (within current k-chunk)
    const int a_row = (lid & 7) + ((lid >> 3) & 1) * 8;   // + mtile base
    const int a_colb = ((lid >> 4) & 1) * 16;             // byte offset (8 bf16)
    const int b_row = (lid & 7) + ((lid >> 4) & 1) * 8;   // + ntile base
    const int b_colb = ((lid >> 3) & 1) * 16;

    for (int c = 0; c < 8; c++) {
        const int kt = c * 64;
        // ---- load A chunk 128x64 fp32 -> bf16 hi/lo ----
        #pragma unroll
        for (int it = 0; it < 8; it++) {
            int idx = tid + it * 256;            // 0..2047
            int row = idx >> 4, kq = idx & 15;   // kq: group of 4 floats
            float4 v = *reinterpret_cast<const float4*>(&A[(size_t)(m0 + row) * 512 + kt + kq * 4]);
            float hx = __bfloat162float(__float2bfloat16(v.x));
            float hy = __bfloat162float(__float2bfloat16(v.y));
            float hz = __bfloat162float(__float2bfloat16(v.z));
            float hw = __bfloat162float(__float2bfloat16(v.w));
            uint2 hv, lv;
            hv.x = pack2(v.x, v.y);           hv.y = pack2(v.z, v.w);
            lv.x = pack2(v.x - hx, v.y - hy); lv.y = pack2(v.z - hz, v.w - hw);
            *reinterpret_cast<uint2*>(pAh + row * RSB + kq * 8) = hv;
            *reinterpret_cast<uint2*>(pAl + row * RSB + kq * 8) = lv;
        }
        // ---- load B chunk 128x64 bf16 hi & lo ----
        #pragma unroll
        for (int it = 0; it < 4; it++) {
            int idx = tid + it * 256;            // 0..1023
            int n = idx >> 3, kq = idx & 7;      // kq: group of 8 bf16
            const size_t base = (size_t)(n0 + n) * 512 + kt + kq * 8;
            *reinterpret_cast<uint4*>(pBh + n * RSB + kq * 16) = *reinterpret_cast<const uint4*>(Bh_g + base);
            *reinterpret_cast<uint4*>(pBl + n * RSB + kq * 16) = *reinterpret_cast<const uint4*>(Bl_g + base);
        }
        __syncthreads();

        #pragma unroll
        for (int ks = 0; ks < 4; ks++) {
            const int kb = ks * 32;  // byte offset of k0 (16 bf16 = 32B)
            uint32_t bh[8], bl[8];
            #pragma unroll
            for (int jt = 0; jt < 2; jt++) {   // two x4 loads cover 4 n-tiles
                uint32_t addr = (wn * 32 + jt * 16 + b_row) * RSB + kb + b_colb;
                ldsm4(bh + jt * 4, uBh + addr);
                ldsm4(bl + jt * 4, uBl + addr);
            }
            #pragma unroll
            for (int i = 0; i < 4; i++) {
                uint32_t ah[4], al[4];
                uint32_t addr = (wm * 64 + i * 16 + a_row) * RSB + kb + a_colb;
                ldsm4(ah, uAh + addr);
                ldsm4(al, uAl + addr);
                #pragma unroll
                for (int j = 0; j < 4; j++) {
                    mma16816(acc[i][j], ah, bh + 2 * (j >> 1) * 2 + (j & 1) * 2);
                }
                #pragma unroll
                for (int j = 0; j < 4; j++) {
                    mma16816(acc[i][j], ah, bl + j * 2);
                    mma16816(acc[i][j], al, bh + j * 2);
                }
            }
        }
        __syncthreads();
    }

    // ---- epilogue ----
    const int mb = m0 + wm * 64;
    const int nb = n0 + wn * 32;
    #pragma unroll
    for (int i = 0; i < 4; i++) {
        #pragma unroll
        for (int rhalf = 0; rhalf < 2; rhalf++) {
            const int m = mb + i * 16 + g + rhalf * 8;
            const int b_ = m >> 11, s = m & 2047;
            #pragma unroll
            for (int j = 0; j < 4; j++) {
                const int ncol = nb + j * 8 + 2 * tg;
                float2 o;
                o.x = acc[i][j][rhalf * 2 + 0];
                o.y = acc[i][j][rhalf * 2 + 1];
                if (!qkv) {
                    o.x += bias0[ncol];     o.y += bias0[ncol + 1];
                    if (relu) { o.x = fmaxf(o.x, 0.f); o.y = fmaxf(o.y, 0.f); }
                    *reinterpret_cast<float2*>(C0 + (size_t)m * ldC + ncol) = o;
                } else {
                    const int z = ncol >> 9, rr = ncol & 511;
                    const int h = rr >> 6, a = rr & 63;
                    const float* bias = (z == 0) ? bias0 : (z == 1) ? bias1 : bias2;
                    float* out = (z == 0) ? C0 : (z == 1) ? C1 : C2;
                    o.x += bias[rr]; o.y += bias[rr + 1];
                    *reinterpret_cast<float2*>(
                        out + (((size_t)(b_ * Hh + h) * Slen + s) * 64) + a) = o;
                }
            }
        }
    }
}

// ---------------- flash attention (SIMT fp32, unchanged) ----------------
__global__ __launch_bounds__(256)
void flash_kernel(const float* __restrict__ Q, const float* __restrict__ K,
                  const float* __restrict__ V, float* __restrict__ heads)
{
    extern __shared__ float sm[];
    float* Qs  = sm;
    float* KPs = sm + 64*65;
    float* Vs  = sm + 2*64*65;
    const int s0 = blockIdx.x * 64, h = blockIdx.y, b = blockIdx.z;
    const float* Qbh = Q + ((size_t)(b*Hh + h) * Slen) * Aa;
    const float* Kbh = K + ((size_t)(b*Hh + h) * Slen) * Aa;
    const float* Vbh = V + ((size_t)(b*Hh + h) * Slen) * Aa;
    const int tid = threadIdx.x;
    const int ty = tid / 16, tx = tid % 16;

    #pragma unroll
    for (int it = 0; it < 4; it++) {
        int idx = tid + it * 256;
        int r = idx >> 4, q4 = idx & 15;
        float4 vq = *reinterpret_cast<const float4*>(&Qbh[(size_t)(s0 + r) * Aa + q4 * 4]);
        Qs[r*65+q4*4+0]=vq.x; Qs[r*65+q4*4+1]=vq.y; Qs[r*65+q4*4+2]=vq.z; Qs[r*65+q4*4+3]=vq.w;
    }
    float m_run[4], l_run[4], O[4][4];
    #pragma unroll
    for (int i = 0; i < 4; i++) {
        m_run[i] = -INFINITY; l_run[i] = 0.0f;
        #pragma unroll
        for (int j = 0; j < 4; j++) O[i][j] = 0.0f;
    }
    const float scale = 0.125f;

    for (int c0 = 0; c0 < Slen; c0 += 64) {
        #pragma unroll
        for (int it = 0; it < 4; it++) {
            int idx = tid + it * 256;
            int r = idx >> 4, q4 = idx & 15;
            float4 vk = *reinterpret_cast<const float4*>(&Kbh[(size_t)(c0 + r) * Aa + q4 * 4]);
            KPs[r*65+q4*4+0]=vk.x; KPs[r*65+q4*4+1]=vk.y; KPs[r*65+q4*4+2]=vk.z; KPs[r*65+q4*4+3]=vk.w;
            float4 vv = *reinterpret_cast<const float4*>(&Vbh[(size_t)(c0 + r) * Aa + q4 * 4]);
            Vs[r*65+q4*4+0]=vv.x; Vs[r*65+q4*4+1]=vv.y; Vs[r*65+q4*4+2]=vv.z; Vs[r*65+q4*4+3]=vv.w;
        }
        __syncthreads();
        float sv[4][4] = {};
        #pragma unroll 8
        for (int kk = 0; kk < 64; kk++) {
            float a_[4], b_[4];
            #pragma unroll
            for (int i = 0; i < 4; i++) a_[i] = Qs[(ty*4+i)*65 + kk];
            #pragma unroll
            for (int j = 0; j < 4; j++) b_[j] = KPs[(tx*4+j)*65 + kk];
            #pragma unroll
            for (int i = 0; i < 4; i++)
                #pragma unroll
                for (int j = 0; j < 4; j++)
                    sv[i][j] = fmaf(a_[i], b_[j], sv[i][j]);
        }
        float m_new[4], fac[4], psum[4];
        #pragma unroll
        for (int i = 0; i < 4; i++) {
            float tmax = -INFINITY;
            #pragma unroll
            for (int j = 0; j < 4; j++) { sv[i][j] *= scale; tmax = fmaxf(tmax, sv[i][j]); }
            #pragma unroll
            for (int off = 8; off >= 1; off >>= 1)
                tmax = fmaxf(tmax, __shfl_xor_sync(0xffffffffu, tmax, off));
            m_new[i] = fmaxf(m_run[i], tmax);
            fac[i] = __expf(m_run[i] - m_new[i]);
            float ps = 0.0f;
            #pragma unroll
            for (int j = 0; j < 4; j++) { float p = __expf(sv[i][j] - m_new[i]); sv[i][j] = p; ps += p; }
            #pragma unroll
            for (int off = 8; off >= 1; off >>= 1)
                ps += __shfl_xor_sync(0xffffffffu, ps, off);
            psum[i] = ps;
        }
        #pragma unroll
        for (int i = 0; i < 4; i++) {
            l_run[i] = l_run[i] * fac[i] + psum[i];
            m_run[i] = m_new[i];
            #pragma unroll
            for (int j = 0; j < 4; j++) O[i][j] *= fac[i];
        }
        __syncthreads();
        #pragma unroll
        for (int i = 0; i < 4; i++)
            #pragma unroll
            for (int j = 0; j < 4; j++)
                KPs[(ty*4+i)*65 + tx*4+j] = sv[i][j];
        __syncthreads();
        #pragma unroll 8
        for (int cc = 0; cc < 64; cc++) {
            float p_[4], v_[4];
            #pragma unroll
            for (int i = 0; i < 4; i++) p_[i] = KPs[(ty*4+i)*65 + cc];
            #pragma unroll
            for (int j = 0; j < 4; j++) v_[j] = Vs[cc*65 + tx*4+j];
            #pragma unroll
            for (int i = 0; i < 4; i++)
                #pragma unroll
                for (int j = 0; j < 4; j++)
                    O[i][j] = fmaf(p_[i], v_[j], O[i][j]);
        }
        __syncthreads();
    }
    #pragma unroll
    for (int i = 0; i < 4; i++) {
        float inv = 1.0f / l_run[i];
        int s = s0 + ty*4 + i;
        #pragma unroll
        for (int j = 0; j < 4; j++)
            heads[(((size_t)b * Slen + s) * Hh + h) * Aa + tx*4 + j] = O[i][j] * inv;
    }
}

// ---------------- fused add + LayerNorm ----------------
__global__ __launch_bounds__(256)
void addln_kernel(float* __restrict__ x, const float* __restrict__ t,
                  const float* __restrict__ g, const float* __restrict__ beta)
{
    const int r = blockIdx.x, tid = threadIdx.x;
    float v0 = x[(size_t)r*Dm + tid]       + t[(size_t)r*Dm + tid];
    float v1 = x[(size_t)r*Dm + 256 + tid] + t[(size_t)r*Dm + 256 + tid];
    float s = v0 + v1, ss = v0*v0 + v1*v1;
    #pragma unroll
    for (int off = 16; off >= 1; off >>= 1) {
        s  += __shfl_xor_sync(0xffffffffu, s,  off);
        ss += __shfl_xor_sync(0xffffffffu, ss, off);
    }
    __shared__ float red_s[8], red_ss[8], sm_mean, sm_rstd;
    int wid = tid >> 5, lane = tid & 31;
    if (lane == 0) { red_s[wid] = s; red_ss[wid] = ss; }
    __syncthreads();
    if (tid == 0) {
        float S = 0.f, SS = 0.f;
        #pragma unroll
        for (int w = 0; w < 8; w++) { S += red_s[w]; SS += red_ss[w]; }
        float mean = S * (1.0f / Dm);
        sm_mean = mean;
        sm_rstd = rsqrtf(SS * (1.0f / Dm) - mean * mean + LN_EPS);
    }
    __syncthreads();
    float mean = sm_mean, rstd = sm_rstd;
    x[(size_t)r*Dm + tid]       = (v0 - mean) * rstd * g[tid]       + beta[tid];
    x[(size_t)r*Dm + 256 + tid] = (v1 - mean) * rstd * g[256 + tid] + beta[256 + tid];
}

extern "C" void kernel_launch(void* const* d_in, const int* in_sizes, int n_in,
                              void* d_out, int out_size)
{
    const float* x    = (const float*)d_in[0];
    const float* Wq   = (const float*)d_in[1];
    const float* bq   = (const float*)d_in[2];
    const float* Wk   = (const float*)d_in[3];
    const float* bk   = (const float*)d_in[4];
    const float* Wv   = (const float*)d_in[5];
    const float* bv   = (const float*)d_in[6];
    const float* Wo   = (const float*)d_in[7];
    const float* bo   = (const float*)d_in[8];
    const float* ln1g = (const float*)d_in[9];
    const float* ln1b = (const float*)d_in[10];
    const float* W1   = (const float*)d_in[11];
    const float* b1   = (const float*)d_in[12];
    const float* W2   = (const float*)d_in[13];
    const float* b2   = (const float*)d_in[14];
    const float* ln2g = (const float*)d_in[15];
    const float* ln2b = (const float*)d_in[16];
    const float* Wp   = (const float*)d_in[17];
    const float* bp   = (const float*)d_in[18];

    float *gx, *gq, *gk, *gv, *gh, *gt, *g1;
    cudaGetSymbolAddress((void**)&gx, g_x);
    cudaGetSymbolAddress((void**)&gq, g_q);
    cudaGetSymbolAddress((void**)&gk, g_k);
    cudaGetSymbolAddress((void**)&gv, g_v);
    cudaGetSymbolAddress((void**)&gh, g_heads);
    cudaGetSymbolAddress((void**)&gt, g_tmp);
    cudaGetSymbolAddress((void**)&g1, g_h1);
    __nv_bfloat16 *qkvh, *qkvl, *woh, *wol, *w1h, *w1l, *w2h, *w2l, *wph, *wpl;
    cudaGetSymbolAddress((void**)&qkvh, g_wqkv_h);
    cudaGetSymbolAddress((void**)&qkvl, g_wqkv_l);
    cudaGetSymbolAddress((void**)&woh, g_wo_h);
    cudaGetSymbolAddress((void**)&wol, g_wo_l);
    cudaGetSymbolAddress((void**)&w1h, g_w1_h);
    cudaGetSymbolAddress((void**)&w1l, g_w1_l);
    cudaGetSymbolAddress((void**)&w2h, g_w2_h);
    cudaGetSymbolAddress((void**)&w2l, g_w2_l);
    cudaGetSymbolAddress((void**)&wph, g_wp_h);
    cudaGetSymbolAddress((void**)&wpl, g_wp_l);

    const int flash_smem = 3 * 64 * 65 * (int)sizeof(float);
    cudaFuncSetAttribute(flash_kernel, cudaFuncAttributeMaxDynamicSharedMemorySize, flash_smem);
    const int gemm_smem = 4 * 128 * RSB;   // 73728
    cudaFuncSetAttribute(gemm_mma, cudaFuncAttributeMaxDynamicSharedMemorySize, gemm_smem);

    cudaMemcpyAsync(gx, x, (size_t)Mrows * Dm * sizeof(float), cudaMemcpyDeviceToDevice);

    prep_qkv_w<<<dim3(16, 2, 48), dim3(32, 8)>>>(Wq, Wk, Wv, qkvh, qkvl);
    prep_w<<<dim3(16, 16, 2), dim3(32, 8)>>>(Wo, woh, wol, 512);
    prep_w<<<dim3(16, 16, 2), dim3(32, 8)>>>(W1, w1h, w1l, 512);
    prep_w<<<dim3(16, 16, 2), dim3(32, 8)>>>(W2, w2h, w2l, 512);
    prep_w<<<dim3(16, 8, 1),  dim3(32, 8)>>>(Wp, wph, wpl, 256);

    for (int l = 0; l < Ll; l++) {
        const __nv_bfloat16* qkvh_l = qkvh + (size_t)l * 1536 * 512;
        const __nv_bfloat16* qkvl_l = qkvl + (size_t)l * 1536 * 512;

        // fused QKV projection (N=1536), scatter to Q/K/V [B,H,S,A]
        gemm_mma<<<dim3(12, 32), 256, gemm_smem>>>(gx, qkvh_l, qkvl_l,
            bq + (size_t)l*512, bk + (size_t)l*512, bv + (size_t)l*512,
            gq, gk, gv, 0, 0, 1);

        flash_kernel<<<dim3(Slen/64, Hh, Bsz), 256, flash_smem>>>(gq, gk, gv, gh);

        gemm_mma<<<dim3(4, 32), 256, gemm_smem>>>(gh,
            woh + (size_t)l*512*512, wol + (size_t)l*512*512,
            bo + (size_t)l*512, 0, 0, gt, 0, 0, 512, 0, 0);
        addln_kernel<<<Mrows, 256>>>(gx, gt, ln1g + (size_t)l*Dm, ln1b + (size_t)l*Dm);

        gemm_mma<<<dim3(4, 32), 256, gemm_smem>>>(gx,
            w1h + (size_t)l*512*512, w1l + (size_t)l*512*512,
            b1 + (size_t)l*512, 0, 0, g1, 0, 0, 512, 1, 0);
        gemm_mma<<<dim3(4, 32), 256, gemm_smem>>>(g1,
            w2h + (size_t)l*512*512, w2l + (size_t)l*512*512,
            b2 + (size_t)l*512, 0, 0, gt, 0, 0, 512, 0, 0);
        addln_kernel<<<Mrows, 256>>>(gx, gt, ln2g + (size_t)l*Dm, ln2b + (size_t)l*Dm);
    }

    gemm_mma<<<dim3(2, 32), 256, gemm_smem>>>(gx, wph, wpl,
        bp, 0, 0, (float*)d_out, 0, 0, 256, 0, 0);
}

// round 5
// speedup vs baseline: 2.8703x; 2.2110x over previous
#include <cuda_runtime.h>
#include <cuda_bf16.h>
#include <math.h>
#include <stdint.h>

#define Bsz 2
#define Slen 2048
#define Dm 512
#define Hh 8
#define Aa 64
#define Ll 2
#define Tt 256
#define Mrows (Bsz*Slen)
#define LN_EPS 1e-5f

__device__ float g_x[Mrows*Dm];
__device__ float g_q[Bsz*Hh*Slen*Aa];
__device__ float g_k[Bsz*Hh*Slen*Aa];
__device__ float g_v[Bsz*Hh*Slen*Aa];
__device__ float g_heads[Mrows*Hh*Aa];
__device__ float g_tmp[Mrows*Dm];
__device__ float g_h1[Mrows*Dm];
__device__ __nv_bfloat16 g_wqkv_h[Ll*1536*512];
__device__ __nv_bfloat16 g_wqkv_l[Ll*1536*512];
__device__ __nv_bfloat16 g_wo_h[Ll*512*512];
__device__ __nv_bfloat16 g_wo_l[Ll*512*512];
__device__ __nv_bfloat16 g_w1_h[Ll*512*512];
__device__ __nv_bfloat16 g_w1_l[Ll*512*512];
__device__ __nv_bfloat16 g_w2_h[Ll*512*512];
__device__ __nv_bfloat16 g_w2_l[Ll*512*512];
__device__ __nv_bfloat16 g_wp_h[Tt*512];
__device__ __nv_bfloat16 g_wp_l[Tt*512];

__device__ __forceinline__ uint32_t smem_u32(const void* p) {
    uint32_t a;
    asm("{ .reg .u64 t; cvta.to.shared.u64 t, %1; cvt.u32.u64 %0, t; }" : "=r"(a) : "l"(p));
    return a;
}
__device__ __forceinline__ uint32_t pack2(float x, float y) {
    return (uint32_t)__bfloat16_as_ushort(__float2bfloat16(x)) |
           ((uint32_t)__bfloat16_as_ushort(__float2bfloat16(y)) << 16);
}
__device__ __forceinline__ void ldsm4(uint32_t* r, uint32_t addr) {
    asm volatile("ldmatrix.sync.aligned.m8n8.x4.shared.b16 {%0,%1,%2,%3}, [%4];"
        : "=r"(r[0]), "=r"(r[1]), "=r"(r[2]), "=r"(r[3]) : "r"(addr));
}
__device__ __forceinline__ void ldsm4t(uint32_t* r, uint32_t addr) {
    asm volatile("ldmatrix.sync.aligned.m8n8.x4.trans.shared.b16 {%0,%1,%2,%3}, [%4];"
        : "=r"(r[0]), "=r"(r[1]), "=r"(r[2]), "=r"(r[3]) : "r"(addr));
}
__device__ __forceinline__ void mma16816(float* d, const uint32_t* a, const uint32_t* b) {
    asm volatile("mma.sync.aligned.m16n8k16.row.col.f32.bf16.bf16.f32 "
        "{%0,%1,%2,%3}, {%4,%5,%6,%7}, {%8,%9}, {%0,%1,%2,%3};"
        : "+f"(d[0]), "+f"(d[1]), "+f"(d[2]), "+f"(d[3])
        : "r"(a[0]), "r"(a[1]), "r"(a[2]), "r"(a[3]), "r"(b[0]), "r"(b[1]));
}

#define RS 72
#define RSB 144

// ---- weight prep ----
__global__ void prep_w(const float* __restrict__ W, __nv_bfloat16* __restrict__ hi,
                       __nv_bfloat16* __restrict__ lo, int N)
{
    int l = blockIdx.z;
    const float* Wl = W + (size_t)l * 512 * N;
    __nv_bfloat16* hiL = hi + (size_t)l * N * 512;
    __nv_bfloat16* loL = lo + (size_t)l * N * 512;
    __shared__ float t[32][33];
    int k0 = blockIdx.x * 32, n0 = blockIdx.y * 32;
    for (int i = threadIdx.y; i < 32; i += 8)
        t[i][threadIdx.x] = Wl[(size_t)(k0 + i) * N + n0 + threadIdx.x];
    __syncthreads();
    for (int i = threadIdx.y; i < 32; i += 8) {
        float v = t[threadIdx.x][i];
        __nv_bfloat16 h = __float2bfloat16(v);
        hiL[(size_t)(n0 + i) * 512 + k0 + threadIdx.x] = h;
        loL[(size_t)(n0 + i) * 512 + k0 + threadIdx.x] = __float2bfloat16(v - __bfloat162float(h));
    }
}
__global__ void prep_qkv_w(const float* __restrict__ Wq, const float* __restrict__ Wk,
                           const float* __restrict__ Wv,
                           __nv_bfloat16* __restrict__ hi, __nv_bfloat16* __restrict__ lo)
{
    int bz = blockIdx.z;
    int l = bz / 24, rem = bz % 24, zz = rem / 8, h = rem % 8;
    const float* W = (zz == 0 ? Wq : zz == 1 ? Wk : Wv) + ((size_t)(l * Hh + h)) * Dm * Aa;
    size_t nb = (size_t)l * 1536 + zz * 512 + h * 64;
    __shared__ float t[32][33];
    int d0 = blockIdx.x * 32, a0 = blockIdx.y * 32;
    for (int i = threadIdx.y; i < 32; i += 8)
        t[i][threadIdx.x] = W[(size_t)(d0 + i) * Aa + a0 + threadIdx.x];
    __syncthreads();
    for (int i = threadIdx.y; i < 32; i += 8) {
        float v = t[threadIdx.x][i];
        __nv_bfloat16 hv = __float2bfloat16(v);
        hi[(nb + a0 + i) * 512 + d0 + threadIdx.x] = hv;
        lo[(nb + a0 + i) * 512 + d0 + threadIdx.x] = __float2bfloat16(v - __bfloat162float(hv));
    }
}

// ---------------------------------------------------------------------------
// HMMA GEMM (unchanged from R4 — proven)
// ---------------------------------------------------------------------------
__global__ __launch_bounds__(256)
void gemm_mma(const float* __restrict__ A,
              const __nv_bfloat16* __restrict__ Bh_g, const __nv_bfloat16* __restrict__ Bl_g,
              const float* __restrict__ bias0, const float* __restrict__ bias1,
              const float* __restrict__ bias2,
              float* __restrict__ C0, float* __restrict__ C1, float* __restrict__ C2,
              int ldC, int relu, int qkv)
{
    extern __shared__ char smem[];
    char* pAh = smem;
    char* pAl = smem + 128*RSB;
    char* pBh = smem + 2*128*RSB;
    char* pBl = smem + 3*128*RSB;
    const uint32_t uAh = smem_u32(pAh), uAl = smem_u32(pAl);
    const uint32_t uBh = smem_u32(pBh), uBl = smem_u32(pBl);

    const int tid = threadIdx.x;
    const int wid = tid >> 5, lid = tid & 31;
    const int wm = wid >> 2, wn = wid & 3;
    const int g = lid >> 2, tg = lid & 3;
    const int m0 = blockIdx.y * 128, n0 = blockIdx.x * 128;

    float acc[4][4][4];
    #pragma unroll
    for (int i = 0; i < 4; i++)
        #pragma unroll
        for (int j = 0; j < 4; j++)
            #pragma unroll
            for (int e = 0; e < 4; e++) acc[i][j][e] = 0.0f;

    const int a_row = (lid & 7) + ((lid >> 3) & 1) * 8;
    const int a_colb = ((lid >> 4) & 1) * 16;
    const int b_row = (lid & 7) + ((lid >> 4) & 1) * 8;
    const int b_colb = ((lid >> 3) & 1) * 16;

    for (int c = 0; c < 8; c++) {
        const int kt = c * 64;
        #pragma unroll
        for (int it = 0; it < 8; it++) {
            int idx = tid + it * 256;
            int row = idx >> 4, kq = idx & 15;
            float4 v = *reinterpret_cast<const float4*>(&A[(size_t)(m0 + row) * 512 + kt + kq * 4]);
            float hx = __bfloat162float(__float2bfloat16(v.x));
            float hy = __bfloat162float(__float2bfloat16(v.y));
            float hz = __bfloat162float(__float2bfloat16(v.z));
            float hw = __bfloat162float(__float2bfloat16(v.w));
            uint2 hv, lv;
            hv.x = pack2(v.x, v.y);           hv.y = pack2(v.z, v.w);
            lv.x = pack2(v.x - hx, v.y - hy); lv.y = pack2(v.z - hz, v.w - hw);
            *reinterpret_cast<uint2*>(pAh + row * RSB + kq * 8) = hv;
            *reinterpret_cast<uint2*>(pAl + row * RSB + kq * 8) = lv;
        }
        #pragma unroll
        for (int it = 0; it < 4; it++) {
            int idx = tid + it * 256;
            int n = idx >> 3, kq = idx & 7;
            const size_t base = (size_t)(n0 + n) * 512 + kt + kq * 8;
            *reinterpret_cast<uint4*>(pBh + n * RSB + kq * 16) = *reinterpret_cast<const uint4*>(Bh_g + base);
            *reinterpret_cast<uint4*>(pBl + n * RSB + kq * 16) = *reinterpret_cast<const uint4*>(Bl_g + base);
        }
        __syncthreads();

        #pragma unroll
        for (int ks = 0; ks < 4; ks++) {
            const int kb = ks * 32;
            uint32_t bh[8], bl[8];
            #pragma unroll
            for (int jt = 0; jt < 2; jt++) {
                uint32_t addr = (wn * 32 + jt * 16 + b_row) * RSB + kb + b_colb;
                ldsm4(bh + jt * 4, uBh + addr);
                ldsm4(bl + jt * 4, uBl + addr);
            }
            #pragma unroll
            for (int i = 0; i < 4; i++) {
                uint32_t ah[4], al[4];
                uint32_t addr = (wm * 64 + i * 16 + a_row) * RSB + kb + a_colb;
                ldsm4(ah, uAh + addr);
                ldsm4(al, uAl + addr);
                #pragma unroll
                for (int j = 0; j < 4; j++) {
                    mma16816(acc[i][j], ah, bh + j * 2);
                    mma16816(acc[i][j], ah, bl + j * 2);
                    mma16816(acc[i][j], al, bh + j * 2);
                }
            }
        }
        __syncthreads();
    }

    const int mb = m0 + wm * 64;
    const int nb = n0 + wn * 32;
    #pragma unroll
    for (int i = 0; i < 4; i++) {
        #pragma unroll
        for (int rhalf = 0; rhalf < 2; rhalf++) {
            const int m = mb + i * 16 + g + rhalf * 8;
            const int b_ = m >> 11, s = m & 2047;
            #pragma unroll
            for (int j = 0; j < 4; j++) {
                const int ncol = nb + j * 8 + 2 * tg;
                float2 o;
                o.x = acc[i][j][rhalf * 2 + 0];
                o.y = acc[i][j][rhalf * 2 + 1];
                if (!qkv) {
                    o.x += bias0[ncol];     o.y += bias0[ncol + 1];
                    if (relu) { o.x = fmaxf(o.x, 0.f); o.y = fmaxf(o.y, 0.f); }
                    *reinterpret_cast<float2*>(C0 + (size_t)m * ldC + ncol) = o;
                } else {
                    const int z = ncol >> 9, rr = ncol & 511;
                    const int h = rr >> 6, a = rr & 63;
                    const float* bias = (z == 0) ? bias0 : (z == 1) ? bias1 : bias2;
                    float* out = (z == 0) ? C0 : (z == 1) ? C1 : C2;
                    o.x += bias[rr]; o.y += bias[rr + 1];
                    *reinterpret_cast<float2*>(
                        out + (((size_t)(b_ * Hh + h) * Slen + s) * 64) + a) = o;
                }
            }
        }
    }
}

// ---------------------------------------------------------------------------
// Flash attention, HMMA bf16 hi/lo. CTA: 128 q-rows of one (b,h); 8 warps x 16.
// Chunks of 64 keys. P reused from score regs as A-fragments (no smem trip).
// V consumed via ldmatrix.trans. smem 73728 B.
// ---------------------------------------------------------------------------
__global__ __launch_bounds__(256)
void flash_mma(const float* __restrict__ Q, const float* __restrict__ K,
               const float* __restrict__ V, float* __restrict__ heads)
{
    extern __shared__ char smem[];
    char* pQh = smem;                    // 128 x RSB
    char* pQl = smem + 128*RSB;
    char* pKh = smem + 2*128*RSB;        // 64 x RSB each below
    char* pKl = pKh + 64*RSB;
    char* pVh = pKl + 64*RSB;
    char* pVl = pVh + 64*RSB;
    const uint32_t uQh = smem_u32(pQh), uQl = smem_u32(pQl);
    const uint32_t uKh = smem_u32(pKh), uKl = smem_u32(pKl);
    const uint32_t uVh = smem_u32(pVh), uVl = smem_u32(pVl);

    const int s0 = blockIdx.x * 128, h = blockIdx.y, b = blockIdx.z;
    const float* Qbh = Q + ((size_t)(b*Hh + h) * Slen) * Aa;
    const float* Kbh = K + ((size_t)(b*Hh + h) * Slen) * Aa;
    const float* Vbh = V + ((size_t)(b*Hh + h) * Slen) * Aa;

    const int tid = threadIdx.x;
    const int wid = tid >> 5, lid = tid & 31;

    // load Q tile 128x64 -> hi/lo (pre-scaled by 1/8 so scores come out scaled)
    #pragma unroll
    for (int it = 0; it < 8; it++) {
        int idx = tid + it * 256;
        int row = idx >> 4, kq = idx & 15;
        float4 v = *reinterpret_cast<const float4*>(&Qbh[(size_t)(s0 + row) * Aa + kq * 4]);
        v.x *= 0.125f; v.y *= 0.125f; v.z *= 0.125f; v.w *= 0.125f;
        float hx = __bfloat162float(__float2bfloat16(v.x));
        float hy = __bfloat162float(__float2bfloat16(v.y));
        float hz = __bfloat162float(__float2bfloat16(v.z));
        float hw = __bfloat162float(__float2bfloat16(v.w));
        uint2 hv, lv;
        hv.x = pack2(v.x, v.y);           hv.y = pack2(v.z, v.w);
        lv.x = pack2(v.x - hx, v.y - hy); lv.y = pack2(v.z - hz, v.w - hw);
        *reinterpret_cast<uint2*>(pQh + row * RSB + kq * 8) = hv;
        *reinterpret_cast<uint2*>(pQl + row * RSB + kq * 8) = lv;
    }

    const int a_row = (lid & 7) + ((lid >> 3) & 1) * 8;
    const int a_colb = ((lid >> 4) & 1) * 16;
    const int b_row = (lid & 7) + ((lid >> 4) & 1) * 8;
    const int b_colb = ((lid >> 3) & 1) * 16;
    const int v_row = (lid & 7) + ((lid >> 3) & 1) * 8;     // kc row (trans)
    const int v_colb = ((lid >> 4) & 1) * 16;               // a byte offset

    float m0 = -INFINITY, m1 = -INFINITY, l0 = 0.0f, l1 = 0.0f;
    float accO[8][4];
    #pragma unroll
    for (int j = 0; j < 8; j++)
        #pragma unroll
        for (int e = 0; e < 4; e++) accO[j][e] = 0.0f;

    for (int c0 = 0; c0 < Slen; c0 += 64) {
        __syncthreads();   // previous chunk's K/V fully consumed
        #pragma unroll
        for (int it = 0; it < 4; it++) {
            int idx = tid + it * 256;
            int row = idx >> 4, kq = idx & 15;
            float4 v = *reinterpret_cast<const float4*>(&Kbh[(size_t)(c0 + row) * Aa + kq * 4]);
            float hx = __bfloat162float(__float2bfloat16(v.x));
            float hy = __bfloat162float(__float2bfloat16(v.y));
            float hz = __bfloat162float(__float2bfloat16(v.z));
            float hw = __bfloat162float(__float2bfloat16(v.w));
            uint2 hv, lv;
            hv.x = pack2(v.x, v.y);           hv.y = pack2(v.z, v.w);
            lv.x = pack2(v.x - hx, v.y - hy); lv.y = pack2(v.z - hz, v.w - hw);
            *reinterpret_cast<uint2*>(pKh + row * RSB + kq * 8) = hv;
            *reinterpret_cast<uint2*>(pKl + row * RSB + kq * 8) = lv;
            float4 w = *reinterpret_cast<const float4*>(&Vbh[(size_t)(c0 + row) * Aa + kq * 4]);
            hx = __bfloat162float(__float2bfloat16(w.x));
            hy = __bfloat162float(__float2bfloat16(w.y));
            hz = __bfloat162float(__float2bfloat16(w.z));
            hw = __bfloat162float(__float2bfloat16(w.w));
            hv.x = pack2(w.x, w.y);           hv.y = pack2(w.z, w.w);
            lv.x = pack2(w.x - hx, w.y - hy); lv.y = pack2(w.z - hz, w.w - hw);
            *reinterpret_cast<uint2*>(pVh + row * RSB + kq * 8) = hv;
            *reinterpret_cast<uint2*>(pVl + row * RSB + kq * 8) = lv;
        }
        __syncthreads();

        // S = Q @ K^T (scaled via Q)
        float accS[8][4];
        #pragma unroll
        for (int j = 0; j < 8; j++)
            #pragma unroll
            for (int e = 0; e < 4; e++) accS[j][e] = 0.0f;

        #pragma unroll
        for (int ks = 0; ks < 4; ks++) {
            const int kb = ks * 32;
            uint32_t qh[4], ql[4];
            ldsm4(qh, uQh + (wid * 16 + a_row) * RSB + kb + a_colb);
            ldsm4(ql, uQl + (wid * 16 + a_row) * RSB + kb + a_colb);
            uint32_t kh[16], kl[16];
            #pragma unroll
            for (int jt = 0; jt < 4; jt++) {
                uint32_t addr = (jt * 16 + b_row) * RSB + kb + b_colb;
                ldsm4(kh + jt * 4, uKh + addr);
                ldsm4(kl + jt * 4, uKl + addr);
            }
            #pragma unroll
            for (int j = 0; j < 8; j++) {
                const int base = (j >> 1) * 4 + (j & 1) * 2;
                mma16816(accS[j], qh, kh + base);
                mma16816(accS[j], qh, kl + base);
                mma16816(accS[j], ql, kh + base);
            }
        }

        // online softmax (rows: r_lo = lid>>2, r_hi = +8; 4-lane groups)
        float mx0 = -INFINITY, mx1 = -INFINITY;
        #pragma unroll
        for (int j = 0; j < 8; j++) {
            mx0 = fmaxf(mx0, fmaxf(accS[j][0], accS[j][1]));
            mx1 = fmaxf(mx1, fmaxf(accS[j][2], accS[j][3]));
        }
        mx0 = fmaxf(mx0, __shfl_xor_sync(0xffffffffu, mx0, 1));
        mx0 = fmaxf(mx0, __shfl_xor_sync(0xffffffffu, mx0, 2));
        mx1 = fmaxf(mx1, __shfl_xor_sync(0xffffffffu, mx1, 1));
        mx1 = fmaxf(mx1, __shfl_xor_sync(0xffffffffu, mx1, 2));
        const float mn0 = fmaxf(m0, mx0), mn1 = fmaxf(m1, mx1);
        const float fac0 = __expf(m0 - mn0), fac1 = __expf(m1 - mn1);
        float sum0 = 0.0f, sum1 = 0.0f;
        #pragma unroll
        for (int j = 0; j < 8; j++) {
            accS[j][0] = __expf(accS[j][0] - mn0);
            accS[j][1] = __expf(accS[j][1] - mn0);
            accS[j][2] = __expf(accS[j][2] - mn1);
            accS[j][3] = __expf(accS[j][3] - mn1);
            sum0 += accS[j][0] + accS[j][1];
            sum1 += accS[j][2] + accS[j][3];
        }
        sum0 += __shfl_xor_sync(0xffffffffu, sum0, 1);
        sum0 += __shfl_xor_sync(0xffffffffu, sum0, 2);
        sum1 += __shfl_xor_sync(0xffffffffu, sum1, 1);
        sum1 += __shfl_xor_sync(0xffffffffu, sum1, 2);
        l0 = l0 * fac0 + sum0;  m0 = mn0;
        l1 = l1 * fac1 + sum1;  m1 = mn1;
        #pragma unroll
        for (int j = 0; j < 8; j++) {
            accO[j][0] *= fac0; accO[j][1] *= fac0;
            accO[j][2] *= fac1; accO[j][3] *= fac1;
        }

        // O += P @ V  (P from regs; V^T frags via ldmatrix.trans)
        #pragma unroll
        for (int ks = 0; ks < 4; ks++) {
            uint32_t ph[4], pl[4];
            {
                const float* p0 = accS[2*ks];
                const float* p1 = accS[2*ks + 1];
                float h00 = __bfloat162float(__float2bfloat16(p0[0]));
                float h01 = __bfloat162float(__float2bfloat16(p0[1]));
                float h02 = __bfloat162float(__float2bfloat16(p0[2]));
                float h03 = __bfloat162float(__float2bfloat16(p0[3]));
                float h10 = __bfloat162float(__float2bfloat16(p1[0]));
                float h11 = __bfloat162float(__float2bfloat16(p1[1]));
                float h12 = __bfloat162float(__float2bfloat16(p1[2]));
                float h13 = __bfloat162float(__float2bfloat16(p1[3]));
                ph[0] = pack2(p0[0], p0[1]);  ph[1] = pack2(p0[2], p0[3]);
                ph[2] = pack2(p1[0], p1[1]);  ph[3] = pack2(p1[2], p1[3]);
                pl[0] = pack2(p0[0]-h00, p0[1]-h01);
                pl[1] = pack2(p0[2]-h02, p0[3]-h03);
                pl[2] = pack2(p1[0]-h10, p1[1]-h11);
                pl[3] = pack2(p1[2]-h12, p1[3]-h13);
            }
            uint32_t vh[16], vl[16];
            #pragma unroll
            for (int jt = 0; jt < 4; jt++) {
                uint32_t addr = (ks * 16 + v_row) * RSB + jt * 32 + v_colb;
                ldsm4t(vh + jt * 4, uVh + addr);
                ldsm4t(vl + jt * 4, uVl + addr);
            }
            #pragma unroll
            for (int j = 0; j < 8; j++) {
                const int base = (j >> 1) * 4 + (j & 1) * 2;
                mma16816(accO[j], ph, vh + base);
                mma16816(accO[j], ph, vl + base);
                mma16816(accO[j], pl, vh + base);
            }
        }
    }

    // epilogue: normalize + write heads[b, s, h*64 + a]
    const float inv0 = 1.0f / l0, inv1 = 1.0f / l1;
    const int r0 = s0 + wid * 16 + (lid >> 2);
    const int r1 = r0 + 8;
    #pragma unroll
    for (int j = 0; j < 8; j++) {
        const int a = j * 8 + 2 * (lid & 3);
        float2 o0 = { accO[j][0] * inv0, accO[j][1] * inv0 };
        float2 o1 = { accO[j][2] * inv1, accO[j][3] * inv1 };
        *reinterpret_cast<float2*>(heads + (((size_t)b * Slen + r0) * Hh + h) * Aa + a) = o0;
        *reinterpret_cast<float2*>(heads + (((size_t)b * Slen + r1) * Hh + h) * Aa + a) = o1;
    }
}

// ---------------- fused add + LayerNorm ----------------
__global__ __launch_bounds__(256)
void addln_kernel(float* __restrict__ x, const float* __restrict__ t,
                  const float* __restrict__ g, const float* __restrict__ beta)
{
    const int r = blockIdx.x, tid = threadIdx.x;
    float v0 = x[(size_t)r*Dm + tid]       + t[(size_t)r*Dm + tid];
    float v1 = x[(size_t)r*Dm + 256 + tid] + t[(size_t)r*Dm + 256 + tid];
    float s = v0 + v1, ss = v0*v0 + v1*v1;
    #pragma unroll
    for (int off = 16; off >= 1; off >>= 1) {
        s  += __shfl_xor_sync(0xffffffffu, s,  off);
        ss += __shfl_xor_sync(0xffffffffu, ss, off);
    }
    __shared__ float red_s[8], red_ss[8], sm_mean, sm_rstd;
    int wid = tid >> 5, lane = tid & 31;
    if (lane == 0) { red_s[wid] = s; red_ss[wid] = ss; }
    __syncthreads();
    if (tid == 0) {
        float S = 0.f, SS = 0.f;
        #pragma unroll
        for (int w = 0; w < 8; w++) { S += red_s[w]; SS += red_ss[w]; }
        float mean = S * (1.0f / Dm);
        sm_mean = mean;
        sm_rstd = rsqrtf(SS * (1.0f / Dm) - mean * mean + LN_EPS);
    }
    __syncthreads();
    float mean = sm_mean, rstd = sm_rstd;
    x[(size_t)r*Dm + tid]       = (v0 - mean) * rstd * g[tid]       + beta[tid];
    x[(size_t)r*Dm + 256 + tid] = (v1 - mean) * rstd * g[256 + tid] + beta[256 + tid];
}

extern "C" void kernel_launch(void* const* d_in, const int* in_sizes, int n_in,
                              void* d_out, int out_size)
{
    const float* x    = (const float*)d_in[0];
    const float* Wq   = (const float*)d_in[1];
    const float* bq   = (const float*)d_in[2];
    const float* Wk   = (const float*)d_in[3];
    const float* bk   = (const float*)d_in[4];
    const float* Wv   = (const float*)d_in[5];
    const float* bv   = (const float*)d_in[6];
    const float* Wo   = (const float*)d_in[7];
    const float* bo   = (const float*)d_in[8];
    const float* ln1g = (const float*)d_in[9];
    const float* ln1b = (const float*)d_in[10];
    const float* W1   = (const float*)d_in[11];
    const float* b1   = (const float*)d_in[12];
    const float* W2   = (const float*)d_in[13];
    const float* b2   = (const float*)d_in[14];
    const float* ln2g = (const float*)d_in[15];
    const float* ln2b = (const float*)d_in[16];
    const float* Wp   = (const float*)d_in[17];
    const float* bp   = (const float*)d_in[18];

    float *gx, *gq, *gk, *gv, *gh, *gt, *g1;
    cudaGetSymbolAddress((void**)&gx, g_x);
    cudaGetSymbolAddress((void**)&gq, g_q);
    cudaGetSymbolAddress((void**)&gk, g_k);
    cudaGetSymbolAddress((void**)&gv, g_v);
    cudaGetSymbolAddress((void**)&gh, g_heads);
    cudaGetSymbolAddress((void**)&gt, g_tmp);
    cudaGetSymbolAddress((void**)&g1, g_h1);
    __nv_bfloat16 *qkvh, *qkvl, *woh, *wol, *w1h, *w1l, *w2h, *w2l, *wph, *wpl;
    cudaGetSymbolAddress((void**)&qkvh, g_wqkv_h);
    cudaGetSymbolAddress((void**)&qkvl, g_wqkv_l);
    cudaGetSymbolAddress((void**)&woh, g_wo_h);
    cudaGetSymbolAddress((void**)&wol, g_wo_l);
    cudaGetSymbolAddress((void**)&w1h, g_w1_h);
    cudaGetSymbolAddress((void**)&w1l, g_w1_l);
    cudaGetSymbolAddress((void**)&w2h, g_w2_h);
    cudaGetSymbolAddress((void**)&w2l, g_w2_l);
    cudaGetSymbolAddress((void**)&wph, g_wp_h);
    cudaGetSymbolAddress((void**)&wpl, g_wp_l);

    const int gemm_smem = 4 * 128 * RSB;            // 73728
    const int flash_smem = 2*128*RSB + 4*64*RSB;    // 73728
    cudaFuncSetAttribute(gemm_mma, cudaFuncAttributeMaxDynamicSharedMemorySize, gemm_smem);
    cudaFuncSetAttribute(flash_mma, cudaFuncAttributeMaxDynamicSharedMemorySize, flash_smem);

    cudaMemcpyAsync(gx, x, (size_t)Mrows * Dm * sizeof(float), cudaMemcpyDeviceToDevice);

    prep_qkv_w<<<dim3(16, 2, 48), dim3(32, 8)>>>(Wq, Wk, Wv, qkvh, qkvl);
    prep_w<<<dim3(16, 16, 2), dim3(32, 8)>>>(Wo, woh, wol, 512);
    prep_w<<<dim3(16, 16, 2), dim3(32, 8)>>>(W1, w1h, w1l, 512);
    prep_w<<<dim3(16, 16, 2), dim3(32, 8)>>>(W2, w2h, w2l, 512);
    prep_w<<<dim3(16, 8, 1),  dim3(32, 8)>>>(Wp, wph, wpl, 256);

    for (int l = 0; l < Ll; l++) {
        const __nv_bfloat16* qkvh_l = qkvh + (size_t)l * 1536 * 512;
        const __nv_bfloat16* qkvl_l = qkvl + (size_t)l * 1536 * 512;

        gemm_mma<<<dim3(12, 32), 256, gemm_smem>>>(gx, qkvh_l, qkvl_l,
            bq + (size_t)l*512, bk + (size_t)l*512, bv + (size_t)l*512,
            gq, gk, gv, 0, 0, 1);

        flash_mma<<<dim3(Slen/128, Hh, Bsz), 256, flash_smem>>>(gq, gk, gv, gh);

        gemm_mma<<<dim3(4, 32), 256, gemm_smem>>>(gh,
            woh + (size_t)l*512*512, wol + (size_t)l*512*512,
            bo + (size_t)l*512, 0, 0, gt, 0, 0, 512, 0, 0);
        addln_kernel<<<Mrows, 256>>>(gx, gt, ln1g + (size_t)l*Dm, ln1b + (size_t)l*Dm);

        gemm_mma<<<dim3(4, 32), 256, gemm_smem>>>(gx,
            w1h + (size_t)l*512*512, w1l + (size_t)l*512*512,
            b1 + (size_t)l*512, 0, 0, g1, 0, 0, 512, 1, 0);
        gemm_mma<<<dim3(4, 32), 256, gemm_smem>>>(g1,
            w2h + (size_t)l*512*512, w2l + (size_t)l*512*512,
            b2 + (size_t)l*512, 0, 0, gt, 0, 0, 512, 0, 0);
        addln_kernel<<<Mrows, 256>>>(gx, gt, ln2g + (size_t)l*Dm, ln2b + (size_t)l*Dm);
    }

    gemm_mma<<<dim3(2, 32), 256, gemm_smem>>>(gx, wph, wpl,
        bp, 0, 0, (float*)d_out, 0, 0, 256, 0, 0);
}

// round 6
// speedup vs baseline: 2.9758x; 1.0367x over previous
#include <cuda_runtime.h>
#include <cuda_bf16.h>
#include <math.h>
#include <stdint.h>

#define Bsz 2
#define Slen 2048
#define Dm 512
#define Hh 8
#define Aa 64
#define Ll 2
#define Tt 256
#define Mrows (Bsz*Slen)
#define LN_EPS 1e-5f

// fp32 state
__device__ float g_x[Mrows*Dm];
__device__ float g_tmp[Mrows*Dm];
// bf16 hi/lo activations
__device__ __nv_bfloat16 g_xh[Mrows*Dm],  g_xl[Mrows*Dm];
__device__ __nv_bfloat16 g_qh[Bsz*Hh*Slen*Aa], g_ql[Bsz*Hh*Slen*Aa];
__device__ __nv_bfloat16 g_kh[Bsz*Hh*Slen*Aa], g_kl[Bsz*Hh*Slen*Aa];
__device__ __nv_bfloat16 g_vh[Bsz*Hh*Slen*Aa], g_vl[Bsz*Hh*Slen*Aa];
__device__ __nv_bfloat16 g_hh[Mrows*Dm],  g_hl[Mrows*Dm];
__device__ __nv_bfloat16 g_1h[Mrows*Dm],  g_1l[Mrows*Dm];
// bf16 hi/lo weights [N][K=512]
__device__ __nv_bfloat16 g_wqkv_h[Ll*1536*512], g_wqkv_l[Ll*1536*512];
__device__ __nv_bfloat16 g_wo_h[Ll*512*512],    g_wo_l[Ll*512*512];
__device__ __nv_bfloat16 g_w1_h[Ll*512*512],    g_w1_l[Ll*512*512];
__device__ __nv_bfloat16 g_w2_h[Ll*512*512],    g_w2_l[Ll*512*512];
__device__ __nv_bfloat16 g_wp_h[Tt*512],        g_wp_l[Tt*512];

__device__ __forceinline__ uint32_t smem_u32(const void* p) {
    uint32_t a;
    asm("{ .reg .u64 t; cvta.to.shared.u64 t, %1; cvt.u32.u64 %0, t; }" : "=r"(a) : "l"(p));
    return a;
}
__device__ __forceinline__ uint32_t pack2(float x, float y) {
    return (uint32_t)__bfloat16_as_ushort(__float2bfloat16(x)) |
           ((uint32_t)__bfloat16_as_ushort(__float2bfloat16(y)) << 16);
}
__device__ __forceinline__ void ldsm4(uint32_t* r, uint32_t addr) {
    asm volatile("ldmatrix.sync.aligned.m8n8.x4.shared.b16 {%0,%1,%2,%3}, [%4];"
        : "=r"(r[0]), "=r"(r[1]), "=r"(r[2]), "=r"(r[3]) : "r"(addr));
}
__device__ __forceinline__ void ldsm4t(uint32_t* r, uint32_t addr) {
    asm volatile("ldmatrix.sync.aligned.m8n8.x4.trans.shared.b16 {%0,%1,%2,%3}, [%4];"
        : "=r"(r[0]), "=r"(r[1]), "=r"(r[2]), "=r"(r[3]) : "r"(addr));
}
__device__ __forceinline__ void mma16816(float* d, const uint32_t* a, const uint32_t* b) {
    asm volatile("mma.sync.aligned.m16n8k16.row.col.f32.bf16.bf16.f32 "
        "{%0,%1,%2,%3}, {%4,%5,%6,%7}, {%8,%9}, {%0,%1,%2,%3};"
        : "+f"(d[0]), "+f"(d[1]), "+f"(d[2]), "+f"(d[3])
        : "r"(a[0]), "r"(a[1]), "r"(a[2]), "r"(a[3]), "r"(b[0]), "r"(b[1]));
}

#define RSB 144

// ---- input convert: x fp32 -> g_x + xh/xl ----
__global__ __launch_bounds__(256)
void conv_x(const float* __restrict__ xin, float* __restrict__ xout,
            __nv_bfloat16* __restrict__ xh, __nv_bfloat16* __restrict__ xl)
{
    int i = blockIdx.x * 256 + threadIdx.x;     // pair index, 2 elems each
    float2 v = *reinterpret_cast<const float2*>(xin + 2*i);
    *reinterpret_cast<float2*>(xout + 2*i) = v;
    float hx = __bfloat162float(__float2bfloat16(v.x));
    float hy = __bfloat162float(__float2bfloat16(v.y));
    *reinterpret_cast<uint32_t*>(xh + 2*i) = pack2(v.x, v.y);
    *reinterpret_cast<uint32_t*>(xl + 2*i) = pack2(v.x - hx, v.y - hy);
}

// ---- merged weight prep: transpose [K=512,N] fp32 -> [N][512] bf16 hi/lo ----
// z: 0-1 Wo(l), 2-3 W1(l), 4-5 W2(l), 6 Wp
__global__ void prep_all(const float* __restrict__ Wo, const float* __restrict__ W1,
                         const float* __restrict__ W2, const float* __restrict__ Wp,
                         __nv_bfloat16* __restrict__ woh, __nv_bfloat16* __restrict__ wol,
                         __nv_bfloat16* __restrict__ w1h, __nv_bfloat16* __restrict__ w1l,
                         __nv_bfloat16* __restrict__ w2h, __nv_bfloat16* __restrict__ w2l,
                         __nv_bfloat16* __restrict__ wph, __nv_bfloat16* __restrict__ wpl)
{
    int z = blockIdx.z;
    const float* W; __nv_bfloat16 *hi, *lo; int N;
    if (z < 2)      { W = Wo + (size_t)z*512*512; hi = woh + (size_t)z*512*512; lo = wol + (size_t)z*512*512; N = 512; }
    else if (z < 4) { int l = z-2; W = W1 + (size_t)l*512*512; hi = w1h + (size_t)l*512*512; lo = w1l + (size_t)l*512*512; N = 512; }
    else if (z < 6) { int l = z-4; W = W2 + (size_t)l*512*512; hi = w2h + (size_t)l*512*512; lo = w2l + (size_t)l*512*512; N = 512; }
    else            { W = Wp; hi = wph; lo = wpl; N = 256; }
    int k0 = blockIdx.x * 32, n0 = blockIdx.y * 32;
    if (n0 >= N) return;
    __shared__ float t[32][33];
    for (int i = threadIdx.y; i < 32; i += 8)
        t[i][threadIdx.x] = W[(size_t)(k0 + i) * N + n0 + threadIdx.x];
    __syncthreads();
    for (int i = threadIdx.y; i < 32; i += 8) {
        float v = t[threadIdx.x][i];
        __nv_bfloat16 h = __float2bfloat16(v);
        hi[(size_t)(n0 + i) * 512 + k0 + threadIdx.x] = h;
        lo[(size_t)(n0 + i) * 512 + k0 + threadIdx.x] = __float2bfloat16(v - __bfloat162float(h));
    }
}
__global__ void prep_qkv_w(const float* __restrict__ Wq, const float* __restrict__ Wk,
                           const float* __restrict__ Wv,
                           __nv_bfloat16* __restrict__ hi, __nv_bfloat16* __restrict__ lo)
{
    int bz = blockIdx.z;
    int l = bz / 24, rem = bz % 24, zz = rem / 8, h = rem % 8;
    const float* W = (zz == 0 ? Wq : zz == 1 ? Wk : Wv) + ((size_t)(l * Hh + h)) * Dm * Aa;
    size_t nb = (size_t)l * 1536 + zz * 512 + h * 64;
    __shared__ float t[32][33];
    int d0 = blockIdx.x * 32, a0 = blockIdx.y * 32;
    for (int i = threadIdx.y; i < 32; i += 8)
        t[i][threadIdx.x] = W[(size_t)(d0 + i) * Aa + a0 + threadIdx.x];
    __syncthreads();
    for (int i = threadIdx.y; i < 32; i += 8) {
        float v = t[threadIdx.x][i];
        __nv_bfloat16 hv = __float2bfloat16(v);
        hi[(nb + a0 + i) * 512 + d0 + threadIdx.x] = hv;
        lo[(nb + a0 + i) * 512 + d0 + threadIdx.x] = __float2bfloat16(v - __bfloat162float(hv));
    }
}

// ---------------------------------------------------------------------------
// HMMA GEMM: A is pre-split bf16 hi/lo [M][512]. modes:
// 0: C0 fp32 = acc+bias (relu opt)
// 1: qkv scatter -> (H0/L0, H1/L1, H2/L2) bf16, Q scaled by 0.125
// 2: H0/L0 bf16 = relu(acc+bias) hi/lo
// ---------------------------------------------------------------------------
__global__ __launch_bounds__(256)
void gemm_mma(const __nv_bfloat16* __restrict__ Ah_g, const __nv_bfloat16* __restrict__ Al_g,
              const __nv_bfloat16* __restrict__ Bh_g, const __nv_bfloat16* __restrict__ Bl_g,
              const float* __restrict__ bias0, const float* __restrict__ bias1,
              const float* __restrict__ bias2,
              float* __restrict__ C0,
              __nv_bfloat16* __restrict__ H0, __nv_bfloat16* __restrict__ L0,
              __nv_bfloat16* __restrict__ H1, __nv_bfloat16* __restrict__ L1,
              __nv_bfloat16* __restrict__ H2, __nv_bfloat16* __restrict__ L2,
              int ldC, int relu, int mode)
{
    extern __shared__ char smem[];
    char* pAh = smem;
    char* pAl = smem + 128*RSB;
    char* pBh = smem + 2*128*RSB;
    char* pBl = smem + 3*128*RSB;
    const uint32_t uAh = smem_u32(pAh), uAl = smem_u32(pAl);
    const uint32_t uBh = smem_u32(pBh), uBl = smem_u32(pBl);

    const int tid = threadIdx.x;
    const int wid = tid >> 5, lid = tid & 31;
    const int wm = wid >> 2, wn = wid & 3;
    const int g = lid >> 2, tg = lid & 3;
    const int m0 = blockIdx.y * 128, n0 = blockIdx.x * 128;

    float acc[4][4][4];
    #pragma unroll
    for (int i = 0; i < 4; i++)
        #pragma unroll
        for (int j = 0; j < 4; j++)
            #pragma unroll
            for (int e = 0; e < 4; e++) acc[i][j][e] = 0.0f;

    const int a_row = (lid & 7) + ((lid >> 3) & 1) * 8;
    const int a_colb = ((lid >> 4) & 1) * 16;
    const int b_row = (lid & 7) + ((lid >> 4) & 1) * 8;
    const int b_colb = ((lid >> 3) & 1) * 16;

    for (int c = 0; c < 8; c++) {
        const int kt = c * 64;
        #pragma unroll
        for (int it = 0; it < 4; it++) {
            int idx = tid + it * 256;            // 0..1023
            int row = idx >> 3, kq = idx & 7;
            const size_t base = (size_t)(m0 + row) * 512 + kt + kq * 8;
            *reinterpret_cast<uint4*>(pAh + row * RSB + kq * 16) = *reinterpret_cast<const uint4*>(Ah_g + base);
            *reinterpret_cast<uint4*>(pAl + row * RSB + kq * 16) = *reinterpret_cast<const uint4*>(Al_g + base);
        }
        #pragma unroll
        for (int it = 0; it < 4; it++) {
            int idx = tid + it * 256;
            int n = idx >> 3, kq = idx & 7;
            const size_t base = (size_t)(n0 + n) * 512 + kt + kq * 8;
            *reinterpret_cast<uint4*>(pBh + n * RSB + kq * 16) = *reinterpret_cast<const uint4*>(Bh_g + base);
            *reinterpret_cast<uint4*>(pBl + n * RSB + kq * 16) = *reinterpret_cast<const uint4*>(Bl_g + base);
        }
        __syncthreads();

        #pragma unroll
        for (int ks = 0; ks < 4; ks++) {
            const int kb = ks * 32;
            uint32_t bh[8], bl[8];
            #pragma unroll
            for (int jt = 0; jt < 2; jt++) {
                uint32_t addr = (wn * 32 + jt * 16 + b_row) * RSB + kb + b_colb;
                ldsm4(bh + jt * 4, uBh + addr);
                ldsm4(bl + jt * 4, uBl + addr);
            }
            #pragma unroll
            for (int i = 0; i < 4; i++) {
                uint32_t ah[4], al[4];
                uint32_t addr = (wm * 64 + i * 16 + a_row) * RSB + kb + a_colb;
                ldsm4(ah, uAh + addr);
                ldsm4(al, uAl + addr);
                #pragma unroll
                for (int j = 0; j < 4; j++) {
                    mma16816(acc[i][j], ah, bh + j * 2);
                    mma16816(acc[i][j], ah, bl + j * 2);
                    mma16816(acc[i][j], al, bh + j * 2);
                }
            }
        }
        __syncthreads();
    }

    const int mb = m0 + wm * 64;
    const int nb = n0 + wn * 32;
    #pragma unroll
    for (int i = 0; i < 4; i++) {
        #pragma unroll
        for (int rhalf = 0; rhalf < 2; rhalf++) {
            const int m = mb + i * 16 + g + rhalf * 8;
            const int b_ = m >> 11, s = m & 2047;
            #pragma unroll
            for (int j = 0; j < 4; j++) {
                const int ncol = nb + j * 8 + 2 * tg;
                float vx = acc[i][j][rhalf * 2 + 0];
                float vy = acc[i][j][rhalf * 2 + 1];
                if (mode == 0) {
                    vx += bias0[ncol]; vy += bias0[ncol + 1];
                    if (relu) { vx = fmaxf(vx, 0.f); vy = fmaxf(vy, 0.f); }
                    float2 o = {vx, vy};
                    *reinterpret_cast<float2*>(C0 + (size_t)m * ldC + ncol) = o;
                } else if (mode == 1) {
                    const int z = ncol >> 9, rr = ncol & 511;
                    const int h = rr >> 6, a = rr & 63;
                    const float* bias = (z == 0) ? bias0 : (z == 1) ? bias1 : bias2;
                    vx += bias[rr]; vy += bias[rr + 1];
                    if (z == 0) { vx *= 0.125f; vy *= 0.125f; }
                    __nv_bfloat16* Hp = (z == 0) ? H0 : (z == 1) ? H1 : H2;
                    __nv_bfloat16* Lp = (z == 0) ? L0 : (z == 1) ? L1 : L2;
                    const size_t off = (((size_t)(b_ * Hh + h) * Slen + s) * 64) + a;
                    float hx = __bfloat162float(__float2bfloat16(vx));
                    float hy = __bfloat162float(__float2bfloat16(vy));
                    *reinterpret_cast<uint32_t*>(Hp + off) = pack2(vx, vy);
                    *reinterpret_cast<uint32_t*>(Lp + off) = pack2(vx - hx, vy - hy);
                } else {
                    vx += bias0[ncol]; vy += bias0[ncol + 1];
                    vx = fmaxf(vx, 0.f); vy = fmaxf(vy, 0.f);
                    const size_t off = (size_t)m * ldC + ncol;
                    float hx = __bfloat162float(__float2bfloat16(vx));
                    float hy = __bfloat162float(__float2bfloat16(vy));
                    *reinterpret_cast<uint32_t*>(H0 + off) = pack2(vx, vy);
                    *reinterpret_cast<uint32_t*>(L0 + off) = pack2(vx - hx, vy - hy);
                }
            }
        }
    }
}

// ---------------------------------------------------------------------------
// Flash attention, HMMA, bf16 hi/lo inputs (Q pre-scaled). Heads out hi/lo.
// ---------------------------------------------------------------------------
__global__ __launch_bounds__(256)
void flash_mma(const __nv_bfloat16* __restrict__ Qh, const __nv_bfloat16* __restrict__ Ql,
               const __nv_bfloat16* __restrict__ Kh, const __nv_bfloat16* __restrict__ Kl,
               const __nv_bfloat16* __restrict__ Vh, const __nv_bfloat16* __restrict__ Vl,
               __nv_bfloat16* __restrict__ Oh, __nv_bfloat16* __restrict__ Ol)
{
    extern __shared__ char smem[];
    char* pQh = smem;
    char* pQl = smem + 128*RSB;
    char* pKh = smem + 2*128*RSB;
    char* pKl = pKh + 64*RSB;
    char* pVh = pKl + 64*RSB;
    char* pVl = pVh + 64*RSB;
    const uint32_t uQh = smem_u32(pQh), uQl = smem_u32(pQl);
    const uint32_t uKh = smem_u32(pKh), uKl = smem_u32(pKl);
    const uint32_t uVh = smem_u32(pVh), uVl = smem_u32(pVl);

    const int s0 = blockIdx.x * 128, h = blockIdx.y, b = blockIdx.z;
    const size_t bh_off = ((size_t)(b*Hh + h) * Slen) * Aa;
    const __nv_bfloat16* Qhb = Qh + bh_off; const __nv_bfloat16* Qlb = Ql + bh_off;
    const __nv_bfloat16* Khb = Kh + bh_off; const __nv_bfloat16* Klb = Kl + bh_off;
    const __nv_bfloat16* Vhb = Vh + bh_off; const __nv_bfloat16* Vlb = Vl + bh_off;

    const int tid = threadIdx.x;
    const int wid = tid >> 5, lid = tid & 31;

    #pragma unroll
    for (int it = 0; it < 4; it++) {
        int idx = tid + it * 256;                 // 0..1023
        int row = idx >> 3, kq = idx & 7;
        const size_t base = (size_t)(s0 + row) * Aa + kq * 8;
        *reinterpret_cast<uint4*>(pQh + row * RSB + kq * 16) = *reinterpret_cast<const uint4*>(Qhb + base);
        *reinterpret_cast<uint4*>(pQl + row * RSB + kq * 16) = *reinterpret_cast<const uint4*>(Qlb + base);
    }

    const int a_row = (lid & 7) + ((lid >> 3) & 1) * 8;
    const int a_colb = ((lid >> 4) & 1) * 16;
    const int b_row = (lid & 7) + ((lid >> 4) & 1) * 8;
    const int b_colb = ((lid >> 3) & 1) * 16;
    const int v_row = (lid & 7) + ((lid >> 3) & 1) * 8;
    const int v_colb = ((lid >> 4) & 1) * 16;

    float m0 = -INFINITY, m1 = -INFINITY, l0 = 0.0f, l1 = 0.0f;
    float accO[8][4];
    #pragma unroll
    for (int j = 0; j < 8; j++)
        #pragma unroll
        for (int e = 0; e < 4; e++) accO[j][e] = 0.0f;

    for (int c0 = 0; c0 < Slen; c0 += 64) {
        __syncthreads();
        #pragma unroll
        for (int it = 0; it < 2; it++) {
            int idx = tid + it * 256;             // 0..511
            int row = idx >> 3, kq = idx & 7;
            const size_t base = (size_t)(c0 + row) * Aa + kq * 8;
            *reinterpret_cast<uint4*>(pKh + row * RSB + kq * 16) = *reinterpret_cast<const uint4*>(Khb + base);
            *reinterpret_cast<uint4*>(pKl + row * RSB + kq * 16) = *reinterpret_cast<const uint4*>(Klb + base);
            *reinterpret_cast<uint4*>(pVh + row * RSB + kq * 16) = *reinterpret_cast<const uint4*>(Vhb + base);
            *reinterpret_cast<uint4*>(pVl + row * RSB + kq * 16) = *reinterpret_cast<const uint4*>(Vlb + base);
        }
        __syncthreads();

        float accS[8][4];
        #pragma unroll
        for (int j = 0; j < 8; j++)
            #pragma unroll
            for (int e = 0; e < 4; e++) accS[j][e] = 0.0f;

        #pragma unroll
        for (int ks = 0; ks < 4; ks++) {
            const int kb = ks * 32;
            uint32_t qh[4], ql[4];
            ldsm4(qh, uQh + (wid * 16 + a_row) * RSB + kb + a_colb);
            ldsm4(ql, uQl + (wid * 16 + a_row) * RSB + kb + a_colb);
            uint32_t kh[16], kl[16];
            #pragma unroll
            for (int jt = 0; jt < 4; jt++) {
                uint32_t addr = (jt * 16 + b_row) * RSB + kb + b_colb;
                ldsm4(kh + jt * 4, uKh + addr);
                ldsm4(kl + jt * 4, uKl + addr);
            }
            #pragma unroll
            for (int j = 0; j < 8; j++) {
                const int base = (j >> 1) * 4 + (j & 1) * 2;
                mma16816(accS[j], qh, kh + base);
                mma16816(accS[j], qh, kl + base);
                mma16816(accS[j], ql, kh + base);
            }
        }

        float mx0 = -INFINITY, mx1 = -INFINITY;
        #pragma unroll
        for (int j = 0; j < 8; j++) {
            mx0 = fmaxf(mx0, fmaxf(accS[j][0], accS[j][1]));
            mx1 = fmaxf(mx1, fmaxf(accS[j][2], accS[j][3]));
        }
        mx0 = fmaxf(mx0, __shfl_xor_sync(0xffffffffu, mx0, 1));
        mx0 = fmaxf(mx0, __shfl_xor_sync(0xffffffffu, mx0, 2));
        mx1 = fmaxf(mx1, __shfl_xor_sync(0xffffffffu, mx1, 1));
        mx1 = fmaxf(mx1, __shfl_xor_sync(0xffffffffu, mx1, 2));
        const float mn0 = fmaxf(m0, mx0), mn1 = fmaxf(m1, mx1);
        const float fac0 = __expf(m0 - mn0), fac1 = __expf(m1 - mn1);
        float sum0 = 0.0f, sum1 = 0.0f;
        #pragma unroll
        for (int j = 0; j < 8; j++) {
            accS[j][0] = __expf(accS[j][0] - mn0);
            accS[j][1] = __expf(accS[j][1] - mn0);
            accS[j][2] = __expf(accS[j][2] - mn1);
            accS[j][3] = __expf(accS[j][3] - mn1);
            sum0 += accS[j][0] + accS[j][1];
            sum1 += accS[j][2] + accS[j][3];
        }
        sum0 += __shfl_xor_sync(0xffffffffu, sum0, 1);
        sum0 += __shfl_xor_sync(0xffffffffu, sum0, 2);
        sum1 += __shfl_xor_sync(0xffffffffu, sum1, 1);
        sum1 += __shfl_xor_sync(0xffffffffu, sum1, 2);
        l0 = l0 * fac0 + sum0;  m0 = mn0;
        l1 = l1 * fac1 + sum1;  m1 = mn1;
        #pragma unroll
        for (int j = 0; j < 8; j++) {
            accO[j][0] *= fac0; accO[j][1] *= fac0;
            accO[j][2] *= fac1; accO[j][3] *= fac1;
        }

        #pragma unroll
        for (int ks = 0; ks < 4; ks++) {
            uint32_t ph[4], pl[4];
            {
                const float* p0 = accS[2*ks];
                const float* p1 = accS[2*ks + 1];
                float h00 = __bfloat162float(__float2bfloat16(p0[0]));
                float h01 = __bfloat162float(__float2bfloat16(p0[1]));
                float h02 = __bfloat162float(__float2bfloat16(p0[2]));
                float h03 = __bfloat162float(__float2bfloat16(p0[3]));
                float h10 = __bfloat162float(__float2bfloat16(p1[0]));
                float h11 = __bfloat162float(__float2bfloat16(p1[1]));
                float h12 = __bfloat162float(__float2bfloat16(p1[2]));
                float h13 = __bfloat162float(__float2bfloat16(p1[3]));
                ph[0] = pack2(p0[0], p0[1]);  ph[1] = pack2(p0[2], p0[3]);
                ph[2] = pack2(p1[0], p1[1]);  ph[3] = pack2(p1[2], p1[3]);
                pl[0] = pack2(p0[0]-h00, p0[1]-h01);
                pl[1] = pack2(p0[2]-h02, p0[3]-h03);
                pl[2] = pack2(p1[0]-h10, p1[1]-h11);
                pl[3] = pack2(p1[2]-h12, p1[3]-h13);
            }
            uint32_t vh[16], vl[16];
            #pragma unroll
            for (int jt = 0; jt < 4; jt++) {
                uint32_t addr = (ks * 16 + v_row) * RSB + jt * 32 + v_colb;
                ldsm4t(vh + jt * 4, uVh + addr);
                ldsm4t(vl + jt * 4, uVl + addr);
            }
            #pragma unroll
            for (int j = 0; j < 8; j++) {
                const int base = (j >> 1) * 4 + (j & 1) * 2;
                mma16816(accO[j], ph, vh + base);
                mma16816(accO[j], ph, vl + base);
                mma16816(accO[j], pl, vh + base);
            }
        }
    }

    // epilogue: normalize + write heads hi/lo at [b, s, h*64 + a]
    const float inv0 = 1.0f / l0, inv1 = 1.0f / l1;
    const int r0 = s0 + wid * 16 + (lid >> 2);
    const int r1 = r0 + 8;
    #pragma unroll
    for (int j = 0; j < 8; j++) {
        const int a = j * 8 + 2 * (lid & 3);
        float x0 = accO[j][0] * inv0, y0 = accO[j][1] * inv0;
        float x1 = accO[j][2] * inv1, y1 = accO[j][3] * inv1;
        float hx0 = __bfloat162float(__float2bfloat16(x0));
        float hy0 = __bfloat162float(__float2bfloat16(y0));
        float hx1 = __bfloat162float(__float2bfloat16(x1));
        float hy1 = __bfloat162float(__float2bfloat16(y1));
        const size_t o0 = (((size_t)b * Slen + r0) * Hh + h) * Aa + a;
        const size_t o1 = (((size_t)b * Slen + r1) * Hh + h) * Aa + a;
        *reinterpret_cast<uint32_t*>(Oh + o0) = pack2(x0, y0);
        *reinterpret_cast<uint32_t*>(Ol + o0) = pack2(x0 - hx0, y0 - hy0);
        *reinterpret_cast<uint32_t*>(Oh + o1) = pack2(x1, y1);
        *reinterpret_cast<uint32_t*>(Ol + o1) = pack2(x1 - hx1, y1 - hy1);
    }
}

// ---------------- fused add + LayerNorm: fp32 out + hi/lo out ----------------
__global__ __launch_bounds__(256)
void addln_kernel(float* __restrict__ x, const float* __restrict__ t,
                  const float* __restrict__ g, const float* __restrict__ beta,
                  __nv_bfloat16* __restrict__ xh, __nv_bfloat16* __restrict__ xl)
{
    const int r = blockIdx.x, tid = threadIdx.x;
    const int c = 2 * tid;
    float2 xv = *reinterpret_cast<const float2*>(x + (size_t)r*Dm + c);
    float2 tv = *reinterpret_cast<const float2*>(t + (size_t)r*Dm + c);
    float v0 = xv.x + tv.x, v1 = xv.y + tv.y;
    float s = v0 + v1, ss = v0*v0 + v1*v1;
    #pragma unroll
    for (int off = 16; off >= 1; off >>= 1) {
        s  += __shfl_xor_sync(0xffffffffu, s,  off);
        ss += __shfl_xor_sync(0xffffffffu, ss, off);
    }
    __shared__ float red_s[8], red_ss[8], sm_mean, sm_rstd;
    int wid = tid >> 5, lane = tid & 31;
    if (lane == 0) { red_s[wid] = s; red_ss[wid] = ss; }
    __syncthreads();
    if (tid == 0) {
        float S = 0.f, SS = 0.f;
        #pragma unroll
        for (int w = 0; w < 8; w++) { S += red_s[w]; SS += red_ss[w]; }
        float mean = S * (1.0f / Dm);
        sm_mean = mean;
        sm_rstd = rsqrtf(SS * (1.0f / Dm) - mean * mean + LN_EPS);
    }
    __syncthreads();
    float mean = sm_mean, rstd = sm_rstd;
    float2 gv = *reinterpret_cast<const float2*>(g + c);
    float2 bv = *reinterpret_cast<const float2*>(beta + c);
    float o0 = (v0 - mean) * rstd * gv.x + bv.x;
    float o1 = (v1 - mean) * rstd * gv.y + bv.y;
    float2 ov = {o0, o1};
    *reinterpret_cast<float2*>(x + (size_t)r*Dm + c) = ov;
    float h0 = __bfloat162float(__float2bfloat16(o0));
    float h1 = __bfloat162float(__float2bfloat16(o1));
    *reinterpret_cast<uint32_t*>(xh + (size_t)r*Dm + c) = pack2(o0, o1);
    *reinterpret_cast<uint32_t*>(xl + (size_t)r*Dm + c) = pack2(o0 - h0, o1 - h1);
}

extern "C" void kernel_launch(void* const* d_in, const int* in_sizes, int n_in,
                              void* d_out, int out_size)
{
    const float* x    = (const float*)d_in[0];
    const float* Wq   = (const float*)d_in[1];
    const float* bq   = (const float*)d_in[2];
    const float* Wk   = (const float*)d_in[3];
    const float* bk   = (const float*)d_in[4];
    const float* Wv   = (const float*)d_in[5];
    const float* bv   = (const float*)d_in[6];
    const float* Wo   = (const float*)d_in[7];
    const float* bo   = (const float*)d_in[8];
    const float* ln1g = (const float*)d_in[9];
    const float* ln1b = (const float*)d_in[10];
    const float* W1   = (const float*)d_in[11];
    const float* b1   = (const float*)d_in[12];
    const float* W2   = (const float*)d_in[13];
    const float* b2   = (const float*)d_in[14];
    const float* ln2g = (const float*)d_in[15];
    const float* ln2b = (const float*)d_in[16];
    const float* Wp   = (const float*)d_in[17];
    const float* bp   = (const float*)d_in[18];

    float *gx, *gt;
    cudaGetSymbolAddress((void**)&gx, g_x);
    cudaGetSymbolAddress((void**)&gt, g_tmp);
    __nv_bfloat16 *xh, *xl, *qh, *ql, *kh, *kl, *vh, *vl, *hh, *hl, *oh1, *ol1;
    cudaGetSymbolAddress((void**)&xh, g_xh); cudaGetSymbolAddress((void**)&xl, g_xl);
    cudaGetSymbolAddress((void**)&qh, g_qh); cudaGetSymbolAddress((void**)&ql, g_ql);
    cudaGetSymbolAddress((void**)&kh, g_kh); cudaGetSymbolAddress((void**)&kl, g_kl);
    cudaGetSymbolAddress((void**)&vh, g_vh); cudaGetSymbolAddress((void**)&vl, g_vl);
    cudaGetSymbolAddress((void**)&hh, g_hh); cudaGetSymbolAddress((void**)&hl, g_hl);
    cudaGetSymbolAddress((void**)&oh1, g_1h); cudaGetSymbolAddress((void**)&ol1, g_1l);
    __nv_bfloat16 *qkvh, *qkvl, *woh, *wol, *w1h, *w1l, *w2h, *w2l, *wph, *wpl;
    cudaGetSymbolAddress((void**)&qkvh, g_wqkv_h);
    cudaGetSymbolAddress((void**)&qkvl, g_wqkv_l);
    cudaGetSymbolAddress((void**)&woh, g_wo_h);
    cudaGetSymbolAddress((void**)&wol, g_wo_l);
    cudaGetSymbolAddress((void**)&w1h, g_w1_h);
    cudaGetSymbolAddress((void**)&w1l, g_w1_l);
    cudaGetSymbolAddress((void**)&w2h, g_w2_h);
    cudaGetSymbolAddress((void**)&w2l, g_w2_l);
    cudaGetSymbolAddress((void**)&wph, g_wp_h);
    cudaGetSymbolAddress((void**)&wpl, g_wp_l);

    const int gemm_smem = 4 * 128 * RSB;
    const int flash_smem = 2*128*RSB + 4*64*RSB;
    cudaFuncSetAttribute(gemm_mma, cudaFuncAttributeMaxDynamicSharedMemorySize, gemm_smem);
    cudaFuncSetAttribute(flash_mma, cudaFuncAttributeMaxDynamicSharedMemorySize, flash_smem);

    conv_x<<<Mrows*Dm/512, 256>>>(x, gx, xh, xl);
    prep_qkv_w<<<dim3(16, 2, 48), dim3(32, 8)>>>(Wq, Wk, Wv, qkvh, qkvl);
    prep_all<<<dim3(16, 16, 7), dim3(32, 8)>>>(Wo, W1, W2, Wp,
        woh, wol, w1h, w1l, w2h, w2l, wph, wpl);

    for (int l = 0; l < Ll; l++) {
        const __nv_bfloat16* qkvh_l = qkvh + (size_t)l * 1536 * 512;
        const __nv_bfloat16* qkvl_l = qkvl + (size_t)l * 1536 * 512;

        gemm_mma<<<dim3(12, 32), 256, gemm_smem>>>(xh, xl, qkvh_l, qkvl_l,
            bq + (size_t)l*512, bk + (size_t)l*512, bv + (size_t)l*512,
            0, qh, ql, kh, kl, vh, vl, 0, 0, 1);

        flash_mma<<<dim3(Slen/128, Hh, Bsz), 256, flash_smem>>>(
            qh, ql, kh, kl, vh, vl, hh, hl);

        gemm_mma<<<dim3(4, 32), 256, gemm_smem>>>(hh, hl,
            woh + (size_t)l*512*512, wol + (size_t)l*512*512,
            bo + (size_t)l*512, 0, 0, gt, 0, 0, 0, 0, 0, 0, 512, 0, 0);
        addln_kernel<<<Mrows, 256>>>(gx, gt, ln1g + (size_t)l*Dm, ln1b + (size_t)l*Dm, xh, xl);

        gemm_mma<<<dim3(4, 32), 256, gemm_smem>>>(xh, xl,
            w1h + (size_t)l*512*512, w1l + (size_t)l*512*512,
            b1 + (size_t)l*512, 0, 0, 0, oh1, ol1, 0, 0, 0, 0, 512, 1, 2);
        gemm_mma<<<dim3(4, 32), 256, gemm_smem>>>(oh1, ol1,
            w2h + (size_t)l*512*512, w2l + (size_t)l*512*512,
            b2 + (size_t)l*512, 0, 0, gt, 0, 0, 0, 0, 0, 0, 512, 0, 0);
        addln_kernel<<<Mrows, 256>>>(gx, gt, ln2g + (size_t)l*Dm, ln2b + (size_t)l*Dm, xh, xl);
    }

    gemm_mma<<<dim3(2, 32), 256, gemm_smem>>>(xh, xl, wph, wpl,
        bp, 0, 0, (float*)d_out, 0, 0, 0, 0, 0, 0, 256, 0, 0);
}

// round 7
// speedup vs baseline: 3.1945x; 1.0735x over previous
#include <cuda_runtime.h>
#include <cuda_bf16.h>
#include <math.h>
#include <stdint.h>

#define Bsz 2
#define Slen 2048
#define Dm 512
#define Hh 8
#define Aa 64
#define Ll 2
#define Tt 256
#define Mrows (Bsz*Slen)
#define LN_EPS 1e-5f

__device__ float g_x[Mrows*Dm];
__device__ float g_tmp[Mrows*Dm];
__device__ __nv_bfloat16 g_xh[Mrows*Dm],  g_xl[Mrows*Dm];
__device__ __nv_bfloat16 g_qh[Bsz*Hh*Slen*Aa], g_ql[Bsz*Hh*Slen*Aa];
__device__ __nv_bfloat16 g_kh[Bsz*Hh*Slen*Aa], g_kl[Bsz*Hh*Slen*Aa];
__device__ __nv_bfloat16 g_vh[Bsz*Hh*Slen*Aa], g_vl[Bsz*Hh*Slen*Aa];
__device__ __nv_bfloat16 g_hh[Mrows*Dm],  g_hl[Mrows*Dm];
__device__ __nv_bfloat16 g_1h[Mrows*Dm],  g_1l[Mrows*Dm];
__device__ __nv_bfloat16 g_wqkv_h[Ll*1536*512], g_wqkv_l[Ll*1536*512];
__device__ __nv_bfloat16 g_wo_h[Ll*512*512],    g_wo_l[Ll*512*512];
__device__ __nv_bfloat16 g_w1_h[Ll*512*512],    g_w1_l[Ll*512*512];
__device__ __nv_bfloat16 g_w2_h[Ll*512*512],    g_w2_l[Ll*512*512];
__device__ __nv_bfloat16 g_wp_h[Tt*512],        g_wp_l[Tt*512];

__device__ __forceinline__ uint32_t smem_u32(const void* p) {
    uint32_t a;
    asm("{ .reg .u64 t; cvta.to.shared.u64 t, %1; cvt.u32.u64 %0, t; }" : "=r"(a) : "l"(p));
    return a;
}
__device__ __forceinline__ uint32_t pack2(float x, float y) {
    return (uint32_t)__bfloat16_as_ushort(__float2bfloat16(x)) |
           ((uint32_t)__bfloat16_as_ushort(__float2bfloat16(y)) << 16);
}
__device__ __forceinline__ void ldsm4(uint32_t* r, uint32_t addr) {
    asm volatile("ldmatrix.sync.aligned.m8n8.x4.shared.b16 {%0,%1,%2,%3}, [%4];"
        : "=r"(r[0]), "=r"(r[1]), "=r"(r[2]), "=r"(r[3]) : "r"(addr));
}
__device__ __forceinline__ void ldsm4t(uint32_t* r, uint32_t addr) {
    asm volatile("ldmatrix.sync.aligned.m8n8.x4.trans.shared.b16 {%0,%1,%2,%3}, [%4];"
        : "=r"(r[0]), "=r"(r[1]), "=r"(r[2]), "=r"(r[3]) : "r"(addr));
}
__device__ __forceinline__ void mma16816(float* d, const uint32_t* a, const uint32_t* b) {
    asm volatile("mma.sync.aligned.m16n8k16.row.col.f32.bf16.bf16.f32 "
        "{%0,%1,%2,%3}, {%4,%5,%6,%7}, {%8,%9}, {%0,%1,%2,%3};"
        : "+f"(d[0]), "+f"(d[1]), "+f"(d[2]), "+f"(d[3])
        : "r"(a[0]), "r"(a[1]), "r"(a[2]), "r"(a[3]), "r"(b[0]), "r"(b[1]));
}
#define CP16(sa, gp) asm volatile("cp.async.cg.shared.global [%0], [%1], 16;" :: "r"(sa), "l"(gp))
#define CP_COMMIT()  asm volatile("cp.async.commit_group;" ::: "memory")
#define CP_WAIT0()   asm volatile("cp.async.wait_group 0;" ::: "memory")
#define CP_WAIT1()   asm volatile("cp.async.wait_group 1;" ::: "memory")
#define CP_WAIT2()   asm volatile("cp.async.wait_group 2;" ::: "memory")

#define RSB 144
#define GSTG (4*128*RSB)   // 73728: gemm stage bytes
#define FSTG (4*64*RSB)    // 36864: flash KV stage bytes

// ---- input convert ----
__global__ __launch_bounds__(256)
void conv_x(const float* __restrict__ xin, float* __restrict__ xout,
            __nv_bfloat16* __restrict__ xh, __nv_bfloat16* __restrict__ xl)
{
    int i = blockIdx.x * 256 + threadIdx.x;
    float2 v = *reinterpret_cast<const float2*>(xin + 2*i);
    *reinterpret_cast<float2*>(xout + 2*i) = v;
    float hx = __bfloat162float(__float2bfloat16(v.x));
    float hy = __bfloat162float(__float2bfloat16(v.y));
    *reinterpret_cast<uint32_t*>(xh + 2*i) = pack2(v.x, v.y);
    *reinterpret_cast<uint32_t*>(xl + 2*i) = pack2(v.x - hx, v.y - hy);
}

// ---- weight prep ----
__global__ void prep_all(const float* __restrict__ Wo, const float* __restrict__ W1,
                         const float* __restrict__ W2, const float* __restrict__ Wp,
                         __nv_bfloat16* __restrict__ woh, __nv_bfloat16* __restrict__ wol,
                         __nv_bfloat16* __restrict__ w1h, __nv_bfloat16* __restrict__ w1l,
                         __nv_bfloat16* __restrict__ w2h, __nv_bfloat16* __restrict__ w2l,
                         __nv_bfloat16* __restrict__ wph, __nv_bfloat16* __restrict__ wpl)
{
    int z = blockIdx.z;
    const float* W; __nv_bfloat16 *hi, *lo; int N;
    if (z < 2)      { W = Wo + (size_t)z*512*512; hi = woh + (size_t)z*512*512; lo = wol + (size_t)z*512*512; N = 512; }
    else if (z < 4) { int l = z-2; W = W1 + (size_t)l*512*512; hi = w1h + (size_t)l*512*512; lo = w1l + (size_t)l*512*512; N = 512; }
    else if (z < 6) { int l = z-4; W = W2 + (size_t)l*512*512; hi = w2h + (size_t)l*512*512; lo = w2l + (size_t)l*512*512; N = 512; }
    else            { W = Wp; hi = wph; lo = wpl; N = 256; }
    int k0 = blockIdx.x * 32, n0 = blockIdx.y * 32;
    if (n0 >= N) return;
    __shared__ float t[32][33];
    for (int i = threadIdx.y; i < 32; i += 8)
        t[i][threadIdx.x] = W[(size_t)(k0 + i) * N + n0 + threadIdx.x];
    __syncthreads();
    for (int i = threadIdx.y; i < 32; i += 8) {
        float v = t[threadIdx.x][i];
        __nv_bfloat16 h = __float2bfloat16(v);
        hi[(size_t)(n0 + i) * 512 + k0 + threadIdx.x] = h;
        lo[(size_t)(n0 + i) * 512 + k0 + threadIdx.x] = __float2bfloat16(v - __bfloat162float(h));
    }
}
__global__ void prep_qkv_w(const float* __restrict__ Wq, const float* __restrict__ Wk,
                           const float* __restrict__ Wv,
                           __nv_bfloat16* __restrict__ hi, __nv_bfloat16* __restrict__ lo)
{
    int bz = blockIdx.z;
    int l = bz / 24, rem = bz % 24, zz = rem / 8, h = rem % 8;
    const float* W = (zz == 0 ? Wq : zz == 1 ? Wk : Wv) + ((size_t)(l * Hh + h)) * Dm * Aa;
    size_t nb = (size_t)l * 1536 + zz * 512 + h * 64;
    __shared__ float t[32][33];
    int d0 = blockIdx.x * 32, a0 = blockIdx.y * 32;
    for (int i = threadIdx.y; i < 32; i += 8)
        t[i][threadIdx.x] = W[(size_t)(d0 + i) * Aa + a0 + threadIdx.x];
    __syncthreads();
    for (int i = threadIdx.y; i < 32; i += 8) {
        float v = t[threadIdx.x][i];
        __nv_bfloat16 hv = __float2bfloat16(v);
        hi[(nb + a0 + i) * 512 + d0 + threadIdx.x] = hv;
        lo[(nb + a0 + i) * 512 + d0 + threadIdx.x] = __float2bfloat16(v - __bfloat162float(hv));
    }
}

// ---------------------------------------------------------------------------
// HMMA GEMM, cp.async 3-stage pipeline. smem = 3 * 73728 = 221184 B.
// ---------------------------------------------------------------------------
__global__ __launch_bounds__(256)
void gemm_mma(const __nv_bfloat16* __restrict__ Ah_g, const __nv_bfloat16* __restrict__ Al_g,
              const __nv_bfloat16* __restrict__ Bh_g, const __nv_bfloat16* __restrict__ Bl_g,
              const float* __restrict__ bias0, const float* __restrict__ bias1,
              const float* __restrict__ bias2,
              float* __restrict__ C0,
              __nv_bfloat16* __restrict__ H0, __nv_bfloat16* __restrict__ L0,
              __nv_bfloat16* __restrict__ H1, __nv_bfloat16* __restrict__ L1,
              __nv_bfloat16* __restrict__ H2, __nv_bfloat16* __restrict__ L2,
              int ldC, int relu, int mode)
{
    extern __shared__ char smem[];
    const uint32_t uS = smem_u32(smem);

    const int tid = threadIdx.x;
    const int wid = tid >> 5, lid = tid & 31;
    const int wm = wid >> 2, wn = wid & 3;
    const int g = lid >> 2, tg = lid & 3;
    const int m0 = blockIdx.y * 128, n0 = blockIdx.x * 128;

    float acc[4][4][4];
    #pragma unroll
    for (int i = 0; i < 4; i++)
        #pragma unroll
        for (int j = 0; j < 4; j++)
            #pragma unroll
            for (int e = 0; e < 4; e++) acc[i][j][e] = 0.0f;

    const int a_row = (lid & 7) + ((lid >> 3) & 1) * 8;
    const int a_colb = ((lid >> 4) & 1) * 16;
    const int b_row = (lid & 7) + ((lid >> 4) & 1) * 8;
    const int b_colb = ((lid >> 3) & 1) * 16;

    const int ld_row = tid >> 3, ld_kq = tid & 7;   // 32 rows per pass, 8 kq

    auto load_chunk = [&](int c, int st) {
        const uint32_t sb = uS + (uint32_t)st * GSTG;
        const int kt = c * 64;
        #pragma unroll
        for (int it = 0; it < 4; it++) {
            int row = ld_row + it * 32;
            const size_t ba = (size_t)(m0 + row) * 512 + kt + ld_kq * 8;
            uint32_t so = (uint32_t)(row * RSB + ld_kq * 16);
            CP16(sb + so,            Ah_g + ba);
            CP16(sb + 128*RSB + so,  Al_g + ba);
            const size_t bb = (size_t)(n0 + row) * 512 + kt + ld_kq * 8;
            CP16(sb + 2*128*RSB + so, Bh_g + bb);
            CP16(sb + 3*128*RSB + so, Bl_g + bb);
        }
    };

    load_chunk(0, 0); CP_COMMIT();
    load_chunk(1, 1); CP_COMMIT();
    load_chunk(2, 2); CP_COMMIT();

    for (int c = 0; c < 8; c++) {
        if (c < 6) CP_WAIT2(); else if (c == 6) CP_WAIT1(); else CP_WAIT0();
        __syncthreads();
        const uint32_t sb = uS + (uint32_t)(c % 3) * GSTG;
        const uint32_t uAh = sb, uAl = sb + 128*RSB;
        const uint32_t uBh = sb + 2*128*RSB, uBl = sb + 3*128*RSB;

        #pragma unroll
        for (int ks = 0; ks < 4; ks++) {
            const int kb = ks * 32;
            uint32_t bh[8], bl[8];
            #pragma unroll
            for (int jt = 0; jt < 2; jt++) {
                uint32_t addr = (wn * 32 + jt * 16 + b_row) * RSB + kb + b_colb;
                ldsm4(bh + jt * 4, uBh + addr);
                ldsm4(bl + jt * 4, uBl + addr);
            }
            #pragma unroll
            for (int i = 0; i < 4; i++) {
                uint32_t ah[4], al[4];
                uint32_t addr = (wm * 64 + i * 16 + a_row) * RSB + kb + a_colb;
                ldsm4(ah, uAh + addr);
                ldsm4(al, uAl + addr);
                #pragma unroll
                for (int j = 0; j < 4; j++) {
                    mma16816(acc[i][j], ah, bh + j * 2);
                    mma16816(acc[i][j], ah, bl + j * 2);
                    mma16816(acc[i][j], al, bh + j * 2);
                }
            }
        }
        __syncthreads();
        if (c + 3 < 8) { load_chunk(c + 3, c % 3); CP_COMMIT(); }
    }

    const int mb = m0 + wm * 64;
    const int nb = n0 + wn * 32;
    #pragma unroll
    for (int i = 0; i < 4; i++) {
        #pragma unroll
        for (int rhalf = 0; rhalf < 2; rhalf++) {
            const int m = mb + i * 16 + g + rhalf * 8;
            const int b_ = m >> 11, s = m & 2047;
            #pragma unroll
            for (int j = 0; j < 4; j++) {
                const int ncol = nb + j * 8 + 2 * tg;
                float vx = acc[i][j][rhalf * 2 + 0];
                float vy = acc[i][j][rhalf * 2 + 1];
                if (mode == 0) {
                    vx += bias0[ncol]; vy += bias0[ncol + 1];
                    if (relu) { vx = fmaxf(vx, 0.f); vy = fmaxf(vy, 0.f); }
                    float2 o = {vx, vy};
                    *reinterpret_cast<float2*>(C0 + (size_t)m * ldC + ncol) = o;
                } else if (mode == 1) {
                    const int z = ncol >> 9, rr = ncol & 511;
                    const int h = rr >> 6, a = rr & 63;
                    const float* bias = (z == 0) ? bias0 : (z == 1) ? bias1 : bias2;
                    vx += bias[rr]; vy += bias[rr + 1];
                    if (z == 0) { vx *= 0.125f; vy *= 0.125f; }
                    __nv_bfloat16* Hp = (z == 0) ? H0 : (z == 1) ? H1 : H2;
                    __nv_bfloat16* Lp = (z == 0) ? L0 : (z == 1) ? L1 : L2;
                    const size_t off = (((size_t)(b_ * Hh + h) * Slen + s) * 64) + a;
                    float hx = __bfloat162float(__float2bfloat16(vx));
                    float hy = __bfloat162float(__float2bfloat16(vy));
                    *reinterpret_cast<uint32_t*>(Hp + off) = pack2(vx, vy);
                    *reinterpret_cast<uint32_t*>(Lp + off) = pack2(vx - hx, vy - hy);
                } else {
                    vx += bias0[ncol]; vy += bias0[ncol + 1];
                    vx = fmaxf(vx, 0.f); vy = fmaxf(vy, 0.f);
                    const size_t off = (size_t)m * ldC + ncol;
                    float hx = __bfloat162float(__float2bfloat16(vx));
                    float hy = __bfloat162float(__float2bfloat16(vy));
                    *reinterpret_cast<uint32_t*>(H0 + off) = pack2(vx, vy);
                    *reinterpret_cast<uint32_t*>(L0 + off) = pack2(vx - hx, vy - hy);
                }
            }
        }
    }
}

// ---------------------------------------------------------------------------
// Flash attention, cp.async 2-stage KV pipeline. smem = 36864 + 2*36864.
// ---------------------------------------------------------------------------
__global__ __launch_bounds__(256)
void flash_mma(const __nv_bfloat16* __restrict__ Qh, const __nv_bfloat16* __restrict__ Ql,
               const __nv_bfloat16* __restrict__ Kh, const __nv_bfloat16* __restrict__ Kl,
               const __nv_bfloat16* __restrict__ Vh, const __nv_bfloat16* __restrict__ Vl,
               __nv_bfloat16* __restrict__ Oh, __nv_bfloat16* __restrict__ Ol)
{
    extern __shared__ char smem[];
    const uint32_t uQh = smem_u32(smem);
    const uint32_t uQl = uQh + 128*RSB;
    const uint32_t uKV = uQh + 2*128*RSB;

    const int s0 = blockIdx.x * 128, h = blockIdx.y, b = blockIdx.z;
    const size_t bh_off = ((size_t)(b*Hh + h) * Slen) * Aa;
    const __nv_bfloat16* Qhb = Qh + bh_off; const __nv_bfloat16* Qlb = Ql + bh_off;
    const __nv_bfloat16* Khb = Kh + bh_off; const __nv_bfloat16* Klb = Kl + bh_off;
    const __nv_bfloat16* Vhb = Vh + bh_off; const __nv_bfloat16* Vlb = Vl + bh_off;

    const int tid = threadIdx.x;
    const int wid = tid >> 5, lid = tid & 31;
    const int ld_row = tid >> 3, ld_kq = tid & 7;

    // Q tile via cp.async too (overlaps with first KV loads)
    {
        #pragma unroll
        for (int it = 0; it < 4; it++) {
            int row = ld_row + it * 32;
            const size_t base = (size_t)(s0 + row) * Aa + ld_kq * 8;
            uint32_t so = (uint32_t)(row * RSB + ld_kq * 16);
            CP16(uQh + so, Qhb + base);
            CP16(uQl + so, Qlb + base);
        }
    }

    auto loadKV = [&](int ci, int st) {
        const uint32_t sb = uKV + (uint32_t)st * FSTG;
        const int c0 = ci * 64;
        #pragma unroll
        for (int it = 0; it < 2; it++) {
            int row = ld_row + it * 32;
            const size_t base = (size_t)(c0 + row) * Aa + ld_kq * 8;
            uint32_t so = (uint32_t)(row * RSB + ld_kq * 16);
            CP16(sb + so,           Khb + base);
            CP16(sb + 64*RSB + so,  Klb + base);
            CP16(sb + 2*64*RSB + so, Vhb + base);
            CP16(sb + 3*64*RSB + so, Vlb + base);
        }
    };

    loadKV(0, 0); CP_COMMIT();
    loadKV(1, 1); CP_COMMIT();

    const int a_row = (lid & 7) + ((lid >> 3) & 1) * 8;
    const int a_colb = ((lid >> 4) & 1) * 16;
    const int b_row = (lid & 7) + ((lid >> 4) & 1) * 8;
    const int b_colb = ((lid >> 3) & 1) * 16;
    const int v_row = (lid & 7) + ((lid >> 3) & 1) * 8;
    const int v_colb = ((lid >> 4) & 1) * 16;

    float m0 = -INFINITY, m1 = -INFINITY, l0 = 0.0f, l1 = 0.0f;
    float accO[8][4];
    #pragma unroll
    for (int j = 0; j < 8; j++)
        #pragma unroll
        for (int e = 0; e < 4; e++) accO[j][e] = 0.0f;

    const int NC = Slen / 64;   // 32
    for (int ci = 0; ci < NC; ci++) {
        if (ci == NC - 1) CP_WAIT0(); else CP_WAIT1();
        __syncthreads();
        const uint32_t sb = uKV + (uint32_t)(ci & 1) * FSTG;
        const uint32_t uKh = sb, uKl = sb + 64*RSB;
        const uint32_t uVh = sb + 2*64*RSB, uVl = sb + 3*64*RSB;

        float accS[8][4];
        #pragma unroll
        for (int j = 0; j < 8; j++)
            #pragma unroll
            for (int e = 0; e < 4; e++) accS[j][e] = 0.0f;

        #pragma unroll
        for (int ks = 0; ks < 4; ks++) {
            const int kb = ks * 32;
            uint32_t qh[4], ql[4];
            ldsm4(qh, uQh + (wid * 16 + a_row) * RSB + kb + a_colb);
            ldsm4(ql, uQl + (wid * 16 + a_row) * RSB + kb + a_colb);
            uint32_t kh[16], kl[16];
            #pragma unroll
            for (int jt = 0; jt < 4; jt++) {
                uint32_t addr = (jt * 16 + b_row) * RSB + kb + b_colb;
                ldsm4(kh + jt * 4, uKh + addr);
                ldsm4(kl + jt * 4, uKl + addr);
            }
            #pragma unroll
            for (int j = 0; j < 8; j++) {
                const int base = (j >> 1) * 4 + (j & 1) * 2;
                mma16816(accS[j], qh, kh + base);
                mma16816(accS[j], qh, kl + base);
                mma16816(accS[j], ql, kh + base);
            }
        }

        float mx0 = -INFINITY, mx1 = -INFINITY;
        #pragma unroll
        for (int j = 0; j < 8; j++) {
            mx0 = fmaxf(mx0, fmaxf(accS[j][0], accS[j][1]));
            mx1 = fmaxf(mx1, fmaxf(accS[j][2], accS[j][3]));
        }
        mx0 = fmaxf(mx0, __shfl_xor_sync(0xffffffffu, mx0, 1));
        mx0 = fmaxf(mx0, __shfl_xor_sync(0xffffffffu, mx0, 2));
        mx1 = fmaxf(mx1, __shfl_xor_sync(0xffffffffu, mx1, 1));
        mx1 = fmaxf(mx1, __shfl_xor_sync(0xffffffffu, mx1, 2));
        const float mn0 = fmaxf(m0, mx0), mn1 = fmaxf(m1, mx1);
        const float fac0 = __expf(m0 - mn0), fac1 = __expf(m1 - mn1);
        float sum0 = 0.0f, sum1 = 0.0f;
        #pragma unroll
        for (int j = 0; j < 8; j++) {
            accS[j][0] = __expf(accS[j][0] - mn0);
            accS[j][1] = __expf(accS[j][1] - mn0);
            accS[j][2] = __expf(accS[j][2] - mn1);
            accS[j][3] = __expf(accS[j][3] - mn1);
            sum0 += accS[j][0] + accS[j][1];
            sum1 += accS[j][2] + accS[j][3];
        }
        sum0 += __shfl_xor_sync(0xffffffffu, sum0, 1);
        sum0 += __shfl_xor_sync(0xffffffffu, sum0, 2);
        sum1 += __shfl_xor_sync(0xffffffffu, sum1, 1);
        sum1 += __shfl_xor_sync(0xffffffffu, sum1, 2);
        l0 = l0 * fac0 + sum0;  m0 = mn0;
        l1 = l1 * fac1 + sum1;  m1 = mn1;
        #pragma unroll
        for (int j = 0; j < 8; j++) {
            accO[j][0] *= fac0; accO[j][1] *= fac0;
            accO[j][2] *= fac1; accO[j][3] *= fac1;
        }

        #pragma unroll
        for (int ks = 0; ks < 4; ks++) {
            uint32_t ph[4], pl[4];
            {
                const float* p0 = accS[2*ks];
                const float* p1 = accS[2*ks + 1];
                float h00 = __bfloat162float(__float2bfloat16(p0[0]));
                float h01 = __bfloat162float(__float2bfloat16(p0[1]));
                float h02 = __bfloat162float(__float2bfloat16(p0[2]));
                float h03 = __bfloat162float(__float2bfloat16(p0[3]));
                float h10 = __bfloat162float(__float2bfloat16(p1[0]));
                float h11 = __bfloat162float(__float2bfloat16(p1[1]));
                float h12 = __bfloat162float(__float2bfloat16(p1[2]));
                float h13 = __bfloat162float(__float2bfloat16(p1[3]));
                ph[0] = pack2(p0[0], p0[1]);  ph[1] = pack2(p0[2], p0[3]);
                ph[2] = pack2(p1[0], p1[1]);  ph[3] = pack2(p1[2], p1[3]);
                pl[0] = pack2(p0[0]-h00, p0[1]-h01);
                pl[1] = pack2(p0[2]-h02, p0[3]-h03);
                pl[2] = pack2(p1[0]-h10, p1[1]-h11);
                pl[3] = pack2(p1[2]-h12, p1[3]-h13);
            }
            uint32_t vh[16], vl[16];
            #pragma unroll
            for (int jt = 0; jt < 4; jt++) {
                uint32_t addr = (ks * 16 + v_row) * RSB + jt * 32 + v_colb;
                ldsm4t(vh + jt * 4, uVh + addr);
                ldsm4t(vl + jt * 4, uVl + addr);
            }
            #pragma unroll
            for (int j = 0; j < 8; j++) {
                const int base = (j >> 1) * 4 + (j & 1) * 2;
                mma16816(accO[j], ph, vh + base);
                mma16816(accO[j], ph, vl + base);
                mma16816(accO[j], pl, vh + base);
            }
        }
        __syncthreads();
        if (ci + 2 < NC) { loadKV(ci + 2, ci & 1); CP_COMMIT(); }
    }

    const float inv0 = 1.0f / l0, inv1 = 1.0f / l1;
    const int r0 = s0 + wid * 16 + (lid >> 2);
    const int r1 = r0 + 8;
    #pragma unroll
    for (int j = 0; j < 8; j++) {
        const int a = j * 8 + 2 * (lid & 3);
        float x0 = accO[j][0] * inv0, y0 = accO[j][1] * inv0;
        float x1 = accO[j][2] * inv1, y1 = accO[j][3] * inv1;
        float hx0 = __bfloat162float(__float2bfloat16(x0));
        float hy0 = __bfloat162float(__float2bfloat16(y0));
        float hx1 = __bfloat162float(__float2bfloat16(x1));
        float hy1 = __bfloat162float(__float2bfloat16(y1));
        const size_t o0 = (((size_t)b * Slen + r0) * Hh + h) * Aa + a;
        const size_t o1 = (((size_t)b * Slen + r1) * Hh + h) * Aa + a;
        *reinterpret_cast<uint32_t*>(Oh + o0) = pack2(x0, y0);
        *reinterpret_cast<uint32_t*>(Ol + o0) = pack2(x0 - hx0, y0 - hy0);
        *reinterpret_cast<uint32_t*>(Oh + o1) = pack2(x1, y1);
        *reinterpret_cast<uint32_t*>(Ol + o1) = pack2(x1 - hx1, y1 - hy1);
    }
}

// ---------------- fused add + LayerNorm ----------------
__global__ __launch_bounds__(256)
void addln_kernel(float* __restrict__ x, const float* __restrict__ t,
                  const float* __restrict__ g, const float* __restrict__ beta,
                  __nv_bfloat16* __restrict__ xh, __nv_bfloat16* __restrict__ xl)
{
    const int r = blockIdx.x, tid = threadIdx.x;
    const int c = 2 * tid;
    float2 xv = *reinterpret_cast<const float2*>(x + (size_t)r*Dm + c);
    float2 tv = *reinterpret_cast<const float2*>(t + (size_t)r*Dm + c);
    float v0 = xv.x + tv.x, v1 = xv.y + tv.y;
    float s = v0 + v1, ss = v0*v0 + v1*v1;
    #pragma unroll
    for (int off = 16; off >= 1; off >>= 1) {
        s  += __shfl_xor_sync(0xffffffffu, s,  off);
        ss += __shfl_xor_sync(0xffffffffu, ss, off);
    }
    __shared__ float red_s[8], red_ss[8], sm_mean, sm_rstd;
    int wid = tid >> 5, lane = tid & 31;
    if (lane == 0) { red_s[wid] = s; red_ss[wid] = ss; }
    __syncthreads();
    if (tid == 0) {
        float S = 0.f, SS = 0.f;
        #pragma unroll
        for (int w = 0; w < 8; w++) { S += red_s[w]; SS += red_ss[w]; }
        float mean = S * (1.0f / Dm);
        sm_mean = mean;
        sm_rstd = rsqrtf(SS * (1.0f / Dm) - mean * mean + LN_EPS);
    }
    __syncthreads();
    float mean = sm_mean, rstd = sm_rstd;
    float2 gv = *reinterpret_cast<const float2*>(g + c);
    float2 bv = *reinterpret_cast<const float2*>(beta + c);
    float o0 = (v0 - mean) * rstd * gv.x + bv.x;
    float o1 = (v1 - mean) * rstd * gv.y + bv.y;
    float2 ov = {o0, o1};
    *reinterpret_cast<float2*>(x + (size_t)r*Dm + c) = ov;
    float h0 = __bfloat162float(__float2bfloat16(o0));
    float h1 = __bfloat162float(__float2bfloat16(o1));
    *reinterpret_cast<uint32_t*>(xh + (size_t)r*Dm + c) = pack2(o0, o1);
    *reinterpret_cast<uint32_t*>(xl + (size_t)r*Dm + c) = pack2(o0 - h0, o1 - h1);
}

extern "C" void kernel_launch(void* const* d_in, const int* in_sizes, int n_in,
                              void* d_out, int out_size)
{
    const float* x    = (const float*)d_in[0];
    const float* Wq   = (const float*)d_in[1];
    const float* bq   = (const float*)d_in[2];
    const float* Wk   = (const float*)d_in[3];
    const float* bk   = (const float*)d_in[4];
    const float* Wv   = (const float*)d_in[5];
    const float* bv   = (const float*)d_in[6];
    const float* Wo   = (const float*)d_in[7];
    const float* bo   = (const float*)d_in[8];
    const float* ln1g = (const float*)d_in[9];
    const float* ln1b = (const float*)d_in[10];
    const float* W1   = (const float*)d_in[11];
    const float* b1   = (const float*)d_in[12];
    const float* W2   = (const float*)d_in[13];
    const float* b2   = (const float*)d_in[14];
    const float* ln2g = (const float*)d_in[15];
    const float* ln2b = (const float*)d_in[16];
    const float* Wp   = (const float*)d_in[17];
    const float* bp   = (const float*)d_in[18];

    float *gx, *gt;
    cudaGetSymbolAddress((void**)&gx, g_x);
    cudaGetSymbolAddress((void**)&gt, g_tmp);
    __nv_bfloat16 *xh, *xl, *qh, *ql, *kh, *kl, *vh, *vl, *hh, *hl, *oh1, *ol1;
    cudaGetSymbolAddress((void**)&xh, g_xh); cudaGetSymbolAddress((void**)&xl, g_xl);
    cudaGetSymbolAddress((void**)&qh, g_qh); cudaGetSymbolAddress((void**)&ql, g_ql);
    cudaGetSymbolAddress((void**)&kh, g_kh); cudaGetSymbolAddress((void**)&kl, g_kl);
    cudaGetSymbolAddress((void**)&vh, g_vh); cudaGetSymbolAddress((void**)&vl, g_vl);
    cudaGetSymbolAddress((void**)&hh, g_hh); cudaGetSymbolAddress((void**)&hl, g_hl);
    cudaGetSymbolAddress((void**)&oh1, g_1h); cudaGetSymbolAddress((void**)&ol1, g_1l);
    __nv_bfloat16 *qkvh, *qkvl, *woh, *wol, *w1h, *w1l, *w2h, *w2l, *wph, *wpl;
    cudaGetSymbolAddress((void**)&qkvh, g_wqkv_h);
    cudaGetSymbolAddress((void**)&qkvl, g_wqkv_l);
    cudaGetSymbolAddress((void**)&woh, g_wo_h);
    cudaGetSymbolAddress((void**)&wol, g_wo_l);
    cudaGetSymbolAddress((void**)&w1h, g_w1_h);
    cudaGetSymbolAddress((void**)&w1l, g_w1_l);
    cudaGetSymbolAddress((void**)&w2h, g_w2_h);
    cudaGetSymbolAddress((void**)&w2l, g_w2_l);
    cudaGetSymbolAddress((void**)&wph, g_wp_h);
    cudaGetSymbolAddress((void**)&wpl, g_wp_l);

    const int gemm_smem  = 3 * GSTG;              // 221184
    const int flash_smem = 2*128*RSB + 2 * FSTG;  // 110592
    cudaFuncSetAttribute(gemm_mma, cudaFuncAttributeMaxDynamicSharedMemorySize, gemm_smem);
    cudaFuncSetAttribute(flash_mma, cudaFuncAttributeMaxDynamicSharedMemorySize, flash_smem);

    conv_x<<<Mrows*Dm/512, 256>>>(x, gx, xh, xl);
    prep_qkv_w<<<dim3(16, 2, 48), dim3(32, 8)>>>(Wq, Wk, Wv, qkvh, qkvl);
    prep_all<<<dim3(16, 16, 7), dim3(32, 8)>>>(Wo, W1, W2, Wp,
        woh, wol, w1h, w1l, w2h, w2l, wph, wpl);

    for (int l = 0; l < Ll; l++) {
        const __nv_bfloat16* qkvh_l = qkvh + (size_t)l * 1536 * 512;
        const __nv_bfloat16* qkvl_l = qkvl + (size_t)l * 1536 * 512;

        gemm_mma<<<dim3(12, 32), 256, gemm_smem>>>(xh, xl, qkvh_l, qkvl_l,
            bq + (size_t)l*512, bk + (size_t)l*512, bv + (size_t)l*512,
            0, qh, ql, kh, kl, vh, vl, 0, 0, 1);

        flash_mma<<<dim3(Slen/128, Hh, Bsz), 256, flash_smem>>>(
            qh, ql, kh, kl, vh, vl, hh, hl);

        gemm_mma<<<dim3(4, 32), 256, gemm_smem>>>(hh, hl,
            woh + (size_t)l*512*512, wol + (size_t)l*512*512,
            bo + (size_t)l*512, 0, 0, gt, 0, 0, 0, 0, 0, 0, 512, 0, 0);
        addln_kernel<<<Mrows, 256>>>(gx, gt, ln1g + (size_t)l*Dm, ln1b + (size_t)l*Dm, xh, xl);

        gemm_mma<<<dim3(4, 32), 256, gemm_smem>>>(xh, xl,
            w1h + (size_t)l*512*512, w1l + (size_t)l*512*512,
            b1 + (size_t)l*512, 0, 0, 0, oh1, ol1, 0, 0, 0, 0, 512, 1, 2);
        gemm_mma<<<dim3(4, 32), 256, gemm_smem>>>(oh1, ol1,
            w2h + (size_t)l*512*512, w2l + (size_t)l*512*512,
            b2 + (size_t)l*512, 0, 0, gt, 0, 0, 0, 0, 0, 0, 512, 0, 0);
        addln_kernel<<<Mrows, 256>>>(gx, gt, ln2g + (size_t)l*Dm, ln2b + (size_t)l*Dm, xh, xl);
    }

    gemm_mma<<<dim3(2, 32), 256, gemm_smem>>>(xh, xl, wph, wpl,
        bp, 0, 0, (float*)d_out, 0, 0, 0, 0, 0, 0, 256, 0, 0);
}

// round 8
// speedup vs baseline: 3.2788x; 1.0264x over previous
#include <cuda_runtime.h>
#include <cuda_bf16.h>
#include <math.h>
#include <stdint.h>

#define Bsz 2
#define Slen 2048
#define Dm 512
#define Hh 8
#define Aa 64
#define Ll 2
#define Tt 256
#define Mrows (Bsz*Slen)
#define LN_EPS 1e-5f

__device__ float g_x[Mrows*Dm];
__device__ float g_tmp[Mrows*Dm];
__device__ __nv_bfloat16 g_xh[Mrows*Dm],  g_xl[Mrows*Dm];
__device__ __nv_bfloat16 g_qh[Bsz*Hh*Slen*Aa], g_ql[Bsz*Hh*Slen*Aa];
__device__ __nv_bfloat16 g_kh[Bsz*Hh*Slen*Aa], g_kl[Bsz*Hh*Slen*Aa];
__device__ __nv_bfloat16 g_vh[Bsz*Hh*Slen*Aa], g_vl[Bsz*Hh*Slen*Aa];
__device__ __nv_bfloat16 g_hh[Mrows*Dm],  g_hl[Mrows*Dm];
__device__ __nv_bfloat16 g_1h[Mrows*Dm],  g_1l[Mrows*Dm];
__device__ __nv_bfloat16 g_wqkv_h[Ll*1536*512], g_wqkv_l[Ll*1536*512];
__device__ __nv_bfloat16 g_wo_h[Ll*512*512],    g_wo_l[Ll*512*512];
__device__ __nv_bfloat16 g_w1_h[Ll*512*512],    g_w1_l[Ll*512*512];
__device__ __nv_bfloat16 g_w2_h[Ll*512*512],    g_w2_l[Ll*512*512];
__device__ __nv_bfloat16 g_wp_h[Tt*512],        g_wp_l[Tt*512];

__device__ __forceinline__ uint32_t smem_u32(const void* p) {
    uint32_t a;
    asm("{ .reg .u64 t; cvta.to.shared.u64 t, %1; cvt.u32.u64 %0, t; }" : "=r"(a) : "l"(p));
    return a;
}
__device__ __forceinline__ uint32_t pack2(float x, float y) {
    return (uint32_t)__bfloat16_as_ushort(__float2bfloat16(x)) |
           ((uint32_t)__bfloat16_as_ushort(__float2bfloat16(y)) << 16);
}
__device__ __forceinline__ void ldsm4(uint32_t* r, uint32_t addr) {
    asm volatile("ldmatrix.sync.aligned.m8n8.x4.shared.b16 {%0,%1,%2,%3}, [%4];"
        : "=r"(r[0]), "=r"(r[1]), "=r"(r[2]), "=r"(r[3]) : "r"(addr));
}
__device__ __forceinline__ void ldsm4t(uint32_t* r, uint32_t addr) {
    asm volatile("ldmatrix.sync.aligned.m8n8.x4.trans.shared.b16 {%0,%1,%2,%3}, [%4];"
        : "=r"(r[0]), "=r"(r[1]), "=r"(r[2]), "=r"(r[3]) : "r"(addr));
}
__device__ __forceinline__ void mma16816(float* d, const uint32_t* a, const uint32_t* b) {
    asm volatile("mma.sync.aligned.m16n8k16.row.col.f32.bf16.bf16.f32 "
        "{%0,%1,%2,%3}, {%4,%5,%6,%7}, {%8,%9}, {%0,%1,%2,%3};"
        : "+f"(d[0]), "+f"(d[1]), "+f"(d[2]), "+f"(d[3])
        : "r"(a[0]), "r"(a[1]), "r"(a[2]), "r"(a[3]), "r"(b[0]), "r"(b[1]));
}
#define CP16(sa, gp) asm volatile("cp.async.cg.shared.global [%0], [%1], 16;" :: "r"(sa), "l"(gp))
#define CP_COMMIT()  asm volatile("cp.async.commit_group;" ::: "memory")
#define CP_WAIT0()   asm volatile("cp.async.wait_group 0;" ::: "memory")
#define CP_WAIT1()   asm volatile("cp.async.wait_group 1;" ::: "memory")
#define CP_WAIT2()   asm volatile("cp.async.wait_group 2;" ::: "memory")

#define RSB 144
#define GSTG (4*128*RSB)   // 73728
#define FSTG (4*64*RSB)    // 36864

// ---- input convert ----
__global__ __launch_bounds__(256)
void conv_x(const float* __restrict__ xin, float* __restrict__ xout,
            __nv_bfloat16* __restrict__ xh, __nv_bfloat16* __restrict__ xl)
{
    int i = blockIdx.x * 256 + threadIdx.x;
    float2 v = *reinterpret_cast<const float2*>(xin + 2*i);
    *reinterpret_cast<float2*>(xout + 2*i) = v;
    float hx = __bfloat162float(__float2bfloat16(v.x));
    float hy = __bfloat162float(__float2bfloat16(v.y));
    *reinterpret_cast<uint32_t*>(xh + 2*i) = pack2(v.x, v.y);
    *reinterpret_cast<uint32_t*>(xl + 2*i) = pack2(v.x - hx, v.y - hy);
}

// ---- weight prep ----
__global__ void prep_all(const float* __restrict__ Wo, const float* __restrict__ W1,
                         const float* __restrict__ W2, const float* __restrict__ Wp,
                         __nv_bfloat16* __restrict__ woh, __nv_bfloat16* __restrict__ wol,
                         __nv_bfloat16* __restrict__ w1h, __nv_bfloat16* __restrict__ w1l,
                         __nv_bfloat16* __restrict__ w2h, __nv_bfloat16* __restrict__ w2l,
                         __nv_bfloat16* __restrict__ wph, __nv_bfloat16* __restrict__ wpl)
{
    int z = blockIdx.z;
    const float* W; __nv_bfloat16 *hi, *lo; int N;
    if (z < 2)      { W = Wo + (size_t)z*512*512; hi = woh + (size_t)z*512*512; lo = wol + (size_t)z*512*512; N = 512; }
    else if (z < 4) { int l = z-2; W = W1 + (size_t)l*512*512; hi = w1h + (size_t)l*512*512; lo = w1l + (size_t)l*512*512; N = 512; }
    else if (z < 6) { int l = z-4; W = W2 + (size_t)l*512*512; hi = w2h + (size_t)l*512*512; lo = w2l + (size_t)l*512*512; N = 512; }
    else            { W = Wp; hi = wph; lo = wpl; N = 256; }
    int k0 = blockIdx.x * 32, n0 = blockIdx.y * 32;
    if (n0 >= N) return;
    __shared__ float t[32][33];
    for (int i = threadIdx.y; i < 32; i += 8)
        t[i][threadIdx.x] = W[(size_t)(k0 + i) * N + n0 + threadIdx.x];
    __syncthreads();
    for (int i = threadIdx.y; i < 32; i += 8) {
        float v = t[threadIdx.x][i];
        __nv_bfloat16 h = __float2bfloat16(v);
        hi[(size_t)(n0 + i) * 512 + k0 + threadIdx.x] = h;
        lo[(size_t)(n0 + i) * 512 + k0 + threadIdx.x] = __float2bfloat16(v - __bfloat162float(h));
    }
}
__global__ void prep_qkv_w(const float* __restrict__ Wq, const float* __restrict__ Wk,
                           const float* __restrict__ Wv,
                           __nv_bfloat16* __restrict__ hi, __nv_bfloat16* __restrict__ lo)
{
    int bz = blockIdx.z;
    int l = bz / 24, rem = bz % 24, zz = rem / 8, h = rem % 8;
    const float* W = (zz == 0 ? Wq : zz == 1 ? Wk : Wv) + ((size_t)(l * Hh + h)) * Dm * Aa;
    size_t nb = (size_t)l * 1536 + zz * 512 + h * 64;
    __shared__ float t[32][33];
    int d0 = blockIdx.x * 32, a0 = blockIdx.y * 32;
    for (int i = threadIdx.y; i < 32; i += 8)
        t[i][threadIdx.x] = W[(size_t)(d0 + i) * Aa + a0 + threadIdx.x];
    __syncthreads();
    for (int i = threadIdx.y; i < 32; i += 8) {
        float v = t[threadIdx.x][i];
        __nv_bfloat16 hv = __float2bfloat16(v);
        hi[(nb + a0 + i) * 512 + d0 + threadIdx.x] = hv;
        lo[(nb + a0 + i) * 512 + d0 + threadIdx.x] = __float2bfloat16(v - __bfloat162float(hv));
    }
}

// ---------------------------------------------------------------------------
// HMMA GEMM, 512 threads (16 warps, warp tile 32x32), 3-stage cp.async.
// ---------------------------------------------------------------------------
__global__ __launch_bounds__(512)
void gemm_mma(const __nv_bfloat16* __restrict__ Ah_g, const __nv_bfloat16* __restrict__ Al_g,
              const __nv_bfloat16* __restrict__ Bh_g, const __nv_bfloat16* __restrict__ Bl_g,
              const float* __restrict__ bias0, const float* __restrict__ bias1,
              const float* __restrict__ bias2,
              float* __restrict__ C0,
              __nv_bfloat16* __restrict__ H0, __nv_bfloat16* __restrict__ L0,
              __nv_bfloat16* __restrict__ H1, __nv_bfloat16* __restrict__ L1,
              __nv_bfloat16* __restrict__ H2, __nv_bfloat16* __restrict__ L2,
              int ldC, int relu, int mode)
{
    extern __shared__ char smem[];
    const uint32_t uS = smem_u32(smem);

    const int tid = threadIdx.x;
    const int wid = tid >> 5, lid = tid & 31;
    const int wm = wid >> 2, wn = wid & 3;     // warp tile (wm*32, wn*32)
    const int g = lid >> 2, tg = lid & 3;
    const int m0 = blockIdx.y * 128, n0 = blockIdx.x * 128;

    float acc[2][4][4];
    #pragma unroll
    for (int i = 0; i < 2; i++)
        #pragma unroll
        for (int j = 0; j < 4; j++)
            #pragma unroll
            for (int e = 0; e < 4; e++) acc[i][j][e] = 0.0f;

    const int a_row = (lid & 7) + ((lid >> 3) & 1) * 8;
    const int a_colb = ((lid >> 4) & 1) * 16;
    const int b_row = (lid & 7) + ((lid >> 4) & 1) * 8;
    const int b_colb = ((lid >> 3) & 1) * 16;

    const int ld_row = tid >> 3, ld_kq = tid & 7;   // 64 rows per pass

    auto load_chunk = [&](int c, int st) {
        const uint32_t sb = uS + (uint32_t)st * GSTG;
        const int kt = c * 64;
        #pragma unroll
        for (int it = 0; it < 2; it++) {
            int row = ld_row + it * 64;
            const size_t ba = (size_t)(m0 + row) * 512 + kt + ld_kq * 8;
            uint32_t so = (uint32_t)(row * RSB + ld_kq * 16);
            CP16(sb + so,            Ah_g + ba);
            CP16(sb + 128*RSB + so,  Al_g + ba);
            const size_t bb = (size_t)(n0 + row) * 512 + kt + ld_kq * 8;
            CP16(sb + 2*128*RSB + so, Bh_g + bb);
            CP16(sb + 3*128*RSB + so, Bl_g + bb);
        }
    };

    load_chunk(0, 0); CP_COMMIT();
    load_chunk(1, 1); CP_COMMIT();
    load_chunk(2, 2); CP_COMMIT();

    for (int c = 0; c < 8; c++) {
        if (c < 6) CP_WAIT2(); else if (c == 6) CP_WAIT1(); else CP_WAIT0();
        __syncthreads();
        const uint32_t sb = uS + (uint32_t)(c % 3) * GSTG;
        const uint32_t uAh = sb, uAl = sb + 128*RSB;
        const uint32_t uBh = sb + 2*128*RSB, uBl = sb + 3*128*RSB;

        #pragma unroll
        for (int ks = 0; ks < 4; ks++) {
            const int kb = ks * 32;
            uint32_t bh[8], bl[8];
            #pragma unroll
            for (int jt = 0; jt < 2; jt++) {
                uint32_t addr = (wn * 32 + jt * 16 + b_row) * RSB + kb + b_colb;
                ldsm4(bh + jt * 4, uBh + addr);
                ldsm4(bl + jt * 4, uBl + addr);
            }
            #pragma unroll
            for (int i = 0; i < 2; i++) {
                uint32_t ah[4], al[4];
                uint32_t addr = (wm * 32 + i * 16 + a_row) * RSB + kb + a_colb;
                ldsm4(ah, uAh + addr);
                ldsm4(al, uAl + addr);
                #pragma unroll
                for (int j = 0; j < 4; j++) {
                    mma16816(acc[i][j], ah, bh + j * 2);
                    mma16816(acc[i][j], ah, bl + j * 2);
                    mma16816(acc[i][j], al, bh + j * 2);
                }
            }
        }
        __syncthreads();
        if (c + 3 < 8) { load_chunk(c + 3, c % 3); CP_COMMIT(); }
    }

    const int mb = m0 + wm * 32;
    const int nb = n0 + wn * 32;
    #pragma unroll
    for (int i = 0; i < 2; i++) {
        #pragma unroll
        for (int rhalf = 0; rhalf < 2; rhalf++) {
            const int m = mb + i * 16 + g + rhalf * 8;
            const int b_ = m >> 11, s = m & 2047;
            #pragma unroll
            for (int j = 0; j < 4; j++) {
                const int ncol = nb + j * 8 + 2 * tg;
                float vx = acc[i][j][rhalf * 2 + 0];
                float vy = acc[i][j][rhalf * 2 + 1];
                if (mode == 0) {
                    vx += bias0[ncol]; vy += bias0[ncol + 1];
                    if (relu) { vx = fmaxf(vx, 0.f); vy = fmaxf(vy, 0.f); }
                    float2 o = {vx, vy};
                    *reinterpret_cast<float2*>(C0 + (size_t)m * ldC + ncol) = o;
                } else if (mode == 1) {
                    const int z = ncol >> 9, rr = ncol & 511;
                    const int h = rr >> 6, a = rr & 63;
                    const float* bias = (z == 0) ? bias0 : (z == 1) ? bias1 : bias2;
                    vx += bias[rr]; vy += bias[rr + 1];
                    if (z == 0) { vx *= 0.125f; vy *= 0.125f; }
                    __nv_bfloat16* Hp = (z == 0) ? H0 : (z == 1) ? H1 : H2;
                    __nv_bfloat16* Lp = (z == 0) ? L0 : (z == 1) ? L1 : L2;
                    const size_t off = (((size_t)(b_ * Hh + h) * Slen + s) * 64) + a;
                    float hx = __bfloat162float(__float2bfloat16(vx));
                    float hy = __bfloat162float(__float2bfloat16(vy));
                    *reinterpret_cast<uint32_t*>(Hp + off) = pack2(vx, vy);
                    *reinterpret_cast<uint32_t*>(Lp + off) = pack2(vx - hx, vy - hy);
                } else {
                    vx += bias0[ncol]; vy += bias0[ncol + 1];
                    vx = fmaxf(vx, 0.f); vy = fmaxf(vy, 0.f);
                    const size_t off = (size_t)m * ldC + ncol;
                    float hx = __bfloat162float(__float2bfloat16(vx));
                    float hy = __bfloat162float(__float2bfloat16(vy));
                    *reinterpret_cast<uint32_t*>(H0 + off) = pack2(vx, vy);
                    *reinterpret_cast<uint32_t*>(L0 + off) = pack2(vx - hx, vy - hy);
                }
            }
        }
    }
}

// ---------------------------------------------------------------------------
// Flash attention: 512 threads, 256 q-rows/CTA (16 warps x 16 rows),
// 2-stage cp.async KV pipeline. smem = 73728 + 2*36864 = 147456.
// ---------------------------------------------------------------------------
__global__ __launch_bounds__(512)
void flash_mma(const __nv_bfloat16* __restrict__ Qh, const __nv_bfloat16* __restrict__ Ql,
               const __nv_bfloat16* __restrict__ Kh, const __nv_bfloat16* __restrict__ Kl,
               const __nv_bfloat16* __restrict__ Vh, const __nv_bfloat16* __restrict__ Vl,
               __nv_bfloat16* __restrict__ Oh, __nv_bfloat16* __restrict__ Ol)
{
    extern __shared__ char smem[];
    const uint32_t uQh = smem_u32(smem);
    const uint32_t uQl = uQh + 256*RSB;
    const uint32_t uKV = uQh + 2*256*RSB;

    const int s0 = blockIdx.x * 256, h = blockIdx.y, b = blockIdx.z;
    const size_t bh_off = ((size_t)(b*Hh + h) * Slen) * Aa;
    const __nv_bfloat16* Qhb = Qh + bh_off; const __nv_bfloat16* Qlb = Ql + bh_off;
    const __nv_bfloat16* Khb = Kh + bh_off; const __nv_bfloat16* Klb = Kl + bh_off;
    const __nv_bfloat16* Vhb = Vh + bh_off; const __nv_bfloat16* Vlb = Vl + bh_off;

    const int tid = threadIdx.x;
    const int wid = tid >> 5, lid = tid & 31;
    const int ld_row = tid >> 3, ld_kq = tid & 7;   // 64 rows per pass

    // Q tile 256 rows via cp.async
    #pragma unroll
    for (int it = 0; it < 4; it++) {
        int row = ld_row + it * 64;
        const size_t base = (size_t)(s0 + row) * Aa + ld_kq * 8;
        uint32_t so = (uint32_t)(row * RSB + ld_kq * 16);
        CP16(uQh + so, Qhb + base);
        CP16(uQl + so, Qlb + base);
    }

    auto loadKV = [&](int ci, int st) {
        const uint32_t sb = uKV + (uint32_t)st * FSTG;
        const int c0 = ci * 64;
        const size_t base = (size_t)(c0 + ld_row) * Aa + ld_kq * 8;
        uint32_t so = (uint32_t)(ld_row * RSB + ld_kq * 16);
        CP16(sb + so,            Khb + base);
        CP16(sb + 64*RSB + so,   Klb + base);
        CP16(sb + 2*64*RSB + so, Vhb + base);
        CP16(sb + 3*64*RSB + so, Vlb + base);
    };

    loadKV(0, 0); CP_COMMIT();
    loadKV(1, 1); CP_COMMIT();

    const int a_row = (lid & 7) + ((lid >> 3) & 1) * 8;
    const int a_colb = ((lid >> 4) & 1) * 16;
    const int b_row = (lid & 7) + ((lid >> 4) & 1) * 8;
    const int b_colb = ((lid >> 3) & 1) * 16;
    const int v_row = (lid & 7) + ((lid >> 3) & 1) * 8;
    const int v_colb = ((lid >> 4) & 1) * 16;

    float m0 = -INFINITY, m1 = -INFINITY, l0 = 0.0f, l1 = 0.0f;
    float accO[8][4];
    #pragma unroll
    for (int j = 0; j < 8; j++)
        #pragma unroll
        for (int e = 0; e < 4; e++) accO[j][e] = 0.0f;

    const int NC = Slen / 64;
    for (int ci = 0; ci < NC; ci++) {
        if (ci == NC - 1) CP_WAIT0(); else CP_WAIT1();
        __syncthreads();
        const uint32_t sb = uKV + (uint32_t)(ci & 1) * FSTG;
        const uint32_t uKh = sb, uKl = sb + 64*RSB;
        const uint32_t uVh = sb + 2*64*RSB, uVl = sb + 3*64*RSB;

        float accS[8][4];
        #pragma unroll
        for (int j = 0; j < 8; j++)
            #pragma unroll
            for (int e = 0; e < 4; e++) accS[j][e] = 0.0f;

        #pragma unroll
        for (int ks = 0; ks < 4; ks++) {
            const int kb = ks * 32;
            uint32_t qh[4], ql[4];
            ldsm4(qh, uQh + (wid * 16 + a_row) * RSB + kb + a_colb);
            ldsm4(ql, uQl + (wid * 16 + a_row) * RSB + kb + a_colb);
            uint32_t kh[16], kl[16];
            #pragma unroll
            for (int jt = 0; jt < 4; jt++) {
                uint32_t addr = (jt * 16 + b_row) * RSB + kb + b_colb;
                ldsm4(kh + jt * 4, uKh + addr);
                ldsm4(kl + jt * 4, uKl + addr);
            }
            #pragma unroll
            for (int j = 0; j < 8; j++) {
                const int base = (j >> 1) * 4 + (j & 1) * 2;
                mma16816(accS[j], qh, kh + base);
                mma16816(accS[j], qh, kl + base);
                mma16816(accS[j], ql, kh + base);
            }
        }

        float mx0 = -INFINITY, mx1 = -INFINITY;
        #pragma unroll
        for (int j = 0; j < 8; j++) {
            mx0 = fmaxf(mx0, fmaxf(accS[j][0], accS[j][1]));
            mx1 = fmaxf(mx1, fmaxf(accS[j][2], accS[j][3]));
        }
        mx0 = fmaxf(mx0, __shfl_xor_sync(0xffffffffu, mx0, 1));
        mx0 = fmaxf(mx0, __shfl_xor_sync(0xffffffffu, mx0, 2));
        mx1 = fmaxf(mx1, __shfl_xor_sync(0xffffffffu, mx1, 1));
        mx1 = fmaxf(mx1, __shfl_xor_sync(0xffffffffu, mx1, 2));
        const float mn0 = fmaxf(m0, mx0), mn1 = fmaxf(m1, mx1);
        const float fac0 = __expf(m0 - mn0), fac1 = __expf(m1 - mn1);
        float sum0 = 0.0f, sum1 = 0.0f;
        #pragma unroll
        for (int j = 0; j < 8; j++) {
            accS[j][0] = __expf(accS[j][0] - mn0);
            accS[j][1] = __expf(accS[j][1] - mn0);
            accS[j][2] = __expf(accS[j][2] - mn1);
            accS[j][3] = __expf(accS[j][3] - mn1);
            sum0 += accS[j][0] + accS[j][1];
            sum1 += accS[j][2] + accS[j][3];
        }
        sum0 += __shfl_xor_sync(0xffffffffu, sum0, 1);
        sum0 += __shfl_xor_sync(0xffffffffu, sum0, 2);
        sum1 += __shfl_xor_sync(0xffffffffu, sum1, 1);
        sum1 += __shfl_xor_sync(0xffffffffu, sum1, 2);
        l0 = l0 * fac0 + sum0;  m0 = mn0;
        l1 = l1 * fac1 + sum1;  m1 = mn1;
        #pragma unroll
        for (int j = 0; j < 8; j++) {
            accO[j][0] *= fac0; accO[j][1] *= fac0;
            accO[j][2] *= fac1; accO[j][3] *= fac1;
        }

        #pragma unroll
        for (int ks = 0; ks < 4; ks++) {
            uint32_t ph[4], pl[4];
            {
                const float* p0 = accS[2*ks];
                const float* p1 = accS[2*ks + 1];
                float h00 = __bfloat162float(__float2bfloat16(p0[0]));
                float h01 = __bfloat162float(__float2bfloat16(p0[1]));
                float h02 = __bfloat162float(__float2bfloat16(p0[2]));
                float h03 = __bfloat162float(__float2bfloat16(p0[3]));
                float h10 = __bfloat162float(__float2bfloat16(p1[0]));
                float h11 = __bfloat162float(__float2bfloat16(p1[1]));
                float h12 = __bfloat162float(__float2bfloat16(p1[2]));
                float h13 = __bfloat162float(__float2bfloat16(p1[3]));
                ph[0] = pack2(p0[0], p0[1]);  ph[1] = pack2(p0[2], p0[3]);
                ph[2] = pack2(p1[0], p1[1]);  ph[3] = pack2(p1[2], p1[3]);
                pl[0] = pack2(p0[0]-h00, p0[1]-h01);
                pl[1] = pack2(p0[2]-h02, p0[3]-h03);
                pl[2] = pack2(p1[0]-h10, p1[1]-h11);
                pl[3] = pack2(p1[2]-h12, p1[3]-h13);
            }
            uint32_t vh[16], vl[16];
            #pragma unroll
            for (int jt = 0; jt < 4; jt++) {
                uint32_t addr = (ks * 16 + v_row) * RSB + jt * 32 + v_colb;
                ldsm4t(vh + jt * 4, uVh + addr);
                ldsm4t(vl + jt * 4, uVl + addr);
            }
            #pragma unroll
            for (int j = 0; j < 8; j++) {
                const int base = (j >> 1) * 4 + (j & 1) * 2;
                mma16816(accO[j], ph, vh + base);
                mma16816(accO[j], ph, vl + base);
                mma16816(accO[j], pl, vh + base);
            }
        }
        __syncthreads();
        if (ci + 2 < NC) { loadKV(ci + 2, ci & 1); CP_COMMIT(); }
    }

    const float inv0 = 1.0f / l0, inv1 = 1.0f / l1;
    const int r0 = s0 + wid * 16 + (lid >> 2);
    const int r1 = r0 + 8;
    #pragma unroll
    for (int j = 0; j < 8; j++) {
        const int a = j * 8 + 2 * (lid & 3);
        float x0 = accO[j][0] * inv0, y0 = accO[j][1] * inv0;
        float x1 = accO[j][2] * inv1, y1 = accO[j][3] * inv1;
        float hx0 = __bfloat162float(__float2bfloat16(x0));
        float hy0 = __bfloat162float(__float2bfloat16(y0));
        float hx1 = __bfloat162float(__float2bfloat16(x1));
        float hy1 = __bfloat162float(__float2bfloat16(y1));
        const size_t o0 = (((size_t)b * Slen + r0) * Hh + h) * Aa + a;
        const size_t o1 = (((size_t)b * Slen + r1) * Hh + h) * Aa + a;
        *reinterpret_cast<uint32_t*>(Oh + o0) = pack2(x0, y0);
        *reinterpret_cast<uint32_t*>(Ol + o0) = pack2(x0 - hx0, y0 - hy0);
        *reinterpret_cast<uint32_t*>(Oh + o1) = pack2(x1, y1);
        *reinterpret_cast<uint32_t*>(Ol + o1) = pack2(x1 - hx1, y1 - hy1);
    }
}

// ---------------- fused add + LayerNorm ----------------
__global__ __launch_bounds__(256)
void addln_kernel(float* __restrict__ x, const float* __restrict__ t,
                  const float* __restrict__ g, const float* __restrict__ beta,
                  __nv_bfloat16* __restrict__ xh, __nv_bfloat16* __restrict__ xl)
{
    const int r = blockIdx.x, tid = threadIdx.x;
    const int c = 2 * tid;
    float2 xv = *reinterpret_cast<const float2*>(x + (size_t)r*Dm + c);
    float2 tv = *reinterpret_cast<const float2*>(t + (size_t)r*Dm + c);
    float v0 = xv.x + tv.x, v1 = xv.y + tv.y;
    float s = v0 + v1, ss = v0*v0 + v1*v1;
    #pragma unroll
    for (int off = 16; off >= 1; off >>= 1) {
        s  += __shfl_xor_sync(0xffffffffu, s,  off);
        ss += __shfl_xor_sync(0xffffffffu, ss, off);
    }
    __shared__ float red_s[8], red_ss[8], sm_mean, sm_rstd;
    int wid = tid >> 5, lane = tid & 31;
    if (lane == 0) { red_s[wid] = s; red_ss[wid] = ss; }
    __syncthreads();
    if (tid == 0) {
        float S = 0.f, SS = 0.f;
        #pragma unroll
        for (int w = 0; w < 8; w++) { S += red_s[w]; SS += red_ss[w]; }
        float mean = S * (1.0f / Dm);
        sm_mean = mean;
        sm_rstd = rsqrtf(SS * (1.0f / Dm) - mean * mean + LN_EPS);
    }
    __syncthreads();
    float mean = sm_mean, rstd = sm_rstd;
    float2 gv = *reinterpret_cast<const float2*>(g + c);
    float2 bv = *reinterpret_cast<const float2*>(beta + c);
    float o0 = (v0 - mean) * rstd * gv.x + bv.x;
    float o1 = (v1 - mean) * rstd * gv.y + bv.y;
    float2 ov = {o0, o1};
    *reinterpret_cast<float2*>(x + (size_t)r*Dm + c) = ov;
    float h0 = __bfloat162float(__float2bfloat16(o0));
    float h1 = __bfloat162float(__float2bfloat16(o1));
    *reinterpret_cast<uint32_t*>(xh + (size_t)r*Dm + c) = pack2(o0, o1);
    *reinterpret_cast<uint32_t*>(xl + (size_t)r*Dm + c) = pack2(o0 - h0, o1 - h1);
}

extern "C" void kernel_launch(void* const* d_in, const int* in_sizes, int n_in,
                              void* d_out, int out_size)
{
    const float* x    = (const float*)d_in[0];
    const float* Wq   = (const float*)d_in[1];
    const float* bq   = (const float*)d_in[2];
    const float* Wk   = (const float*)d_in[3];
    const float* bk   = (const float*)d_in[4];
    const float* Wv   = (const float*)d_in[5];
    const float* bv   = (const float*)d_in[6];
    const float* Wo   = (const float*)d_in[7];
    const float* bo   = (const float*)d_in[8];
    const float* ln1g = (const float*)d_in[9];
    const float* ln1b = (const float*)d_in[10];
    const float* W1   = (const float*)d_in[11];
    const float* b1   = (const float*)d_in[12];
    const float* W2   = (const float*)d_in[13];
    const float* b2   = (const float*)d_in[14];
    const float* ln2g = (const float*)d_in[15];
    const float* ln2b = (const float*)d_in[16];
    const float* Wp   = (const float*)d_in[17];
    const float* bp   = (const float*)d_in[18];

    float *gx, *gt;
    cudaGetSymbolAddress((void**)&gx, g_x);
    cudaGetSymbolAddress((void**)&gt, g_tmp);
    __nv_bfloat16 *xh, *xl, *qh, *ql, *kh, *kl, *vh, *vl, *hh, *hl, *oh1, *ol1;
    cudaGetSymbolAddress((void**)&xh, g_xh); cudaGetSymbolAddress((void**)&xl, g_xl);
    cudaGetSymbolAddress((void**)&qh, g_qh); cudaGetSymbolAddress((void**)&ql, g_ql);
    cudaGetSymbolAddress((void**)&kh, g_kh); cudaGetSymbolAddress((void**)&kl, g_kl);
    cudaGetSymbolAddress((void**)&vh, g_vh); cudaGetSymbolAddress((void**)&vl, g_vl);
    cudaGetSymbolAddress((void**)&hh, g_hh); cudaGetSymbolAddress((void**)&hl, g_hl);
    cudaGetSymbolAddress((void**)&oh1, g_1h); cudaGetSymbolAddress((void**)&ol1, g_1l);
    __nv_bfloat16 *qkvh, *qkvl, *woh, *wol, *w1h, *w1l, *w2h, *w2l, *wph, *wpl;
    cudaGetSymbolAddress((void**)&qkvh, g_wqkv_h);
    cudaGetSymbolAddress((void**)&qkvl, g_wqkv_l);
    cudaGetSymbolAddress((void**)&woh, g_wo_h);
    cudaGetSymbolAddress((void**)&wol, g_wo_l);
    cudaGetSymbolAddress((void**)&w1h, g_w1_h);
    cudaGetSymbolAddress((void**)&w1l, g_w1_l);
    cudaGetSymbolAddress((void**)&w2h, g_w2_h);
    cudaGetSymbolAddress((void**)&w2l, g_w2_l);
    cudaGetSymbolAddress((void**)&wph, g_wp_h);
    cudaGetSymbolAddress((void**)&wpl, g_wp_l);

    const int gemm_smem  = 3 * GSTG;              // 221184
    const int flash_smem = 2*256*RSB + 2 * FSTG;  // 147456
    cudaFuncSetAttribute(gemm_mma, cudaFuncAttributeMaxDynamicSharedMemorySize, gemm_smem);
    cudaFuncSetAttribute(flash_mma, cudaFuncAttributeMaxDynamicSharedMemorySize, flash_smem);

    conv_x<<<Mrows*Dm/512, 256>>>(x, gx, xh, xl);
    prep_qkv_w<<<dim3(16, 2, 48), dim3(32, 8)>>>(Wq, Wk, Wv, qkvh, qkvl);
    prep_all<<<dim3(16, 16, 7), dim3(32, 8)>>>(Wo, W1, W2, Wp,
        woh, wol, w1h, w1l, w2h, w2l, wph, wpl);

    for (int l = 0; l < Ll; l++) {
        const __nv_bfloat16* qkvh_l = qkvh + (size_t)l * 1536 * 512;
        const __nv_bfloat16* qkvl_l = qkvl + (size_t)l * 1536 * 512;

        gemm_mma<<<dim3(12, 32), 512, gemm_smem>>>(xh, xl, qkvh_l, qkvl_l,
            bq + (size_t)l*512, bk + (size_t)l*512, bv + (size_t)l*512,
            0, qh, ql, kh, kl, vh, vl, 0, 0, 1);

        flash_mma<<<dim3(Slen/256, Hh, Bsz), 512, flash_smem>>>(
            qh, ql, kh, kl, vh, vl, hh, hl);

        gemm_mma<<<dim3(4, 32), 512, gemm_smem>>>(hh, hl,
            woh + (size_t)l*512*512, wol + (size_t)l*512*512,
            bo + (size_t)l*512, 0, 0, gt, 0, 0, 0, 0, 0, 0, 512, 0, 0);
        addln_kernel<<<Mrows, 256>>>(gx, gt, ln1g + (size_t)l*Dm, ln1b + (size_t)l*Dm, xh, xl);

        gemm_mma<<<dim3(4, 32), 512, gemm_smem>>>(xh, xl,
            w1h + (size_t)l*512*512, w1l + (size_t)l*512*512,
            b1 + (size_t)l*512, 0, 0, 0, oh1, ol1, 0, 0, 0, 0, 512, 1, 2);
        gemm_mma<<<dim3(4, 32), 512, gemm_smem>>>(oh1, ol1,
            w2h + (size_t)l*512*512, w2l + (size_t)l*512*512,
            b2 + (size_t)l*512, 0, 0, gt, 0, 0, 0, 0, 0, 0, 512, 0, 0);
        addln_kernel<<<Mrows, 256>>>(gx, gt, ln2g + (size_t)l*Dm, ln2b + (size_t)l*Dm, xh, xl);
    }

    gemm_mma<<<dim3(2, 32), 512, gemm_smem>>>(xh, xl, wph, wpl,
        bp, 0, 0, (float*)d_out, 0, 0, 0, 0, 0, 0, 256, 0, 0);
}